// round 1
// baseline (speedup 1.0000x reference)
#include <cuda_runtime.h>
#include <cuda_bf16.h>
#include <math.h>

#define HW 128
#define NPIX (HW*HW)          // 16384
#define TOPK 300
#define NLINES 20000
#define DIM_LOI 128
#define NPTS0 32
#define NPTS1 8
#define DIM_FC 1024
#define NLAB 3

// ---------------- scratch (device globals; no allocation allowed) ----------
__device__ float g_loiT[NPIX * DIM_LOI];          // [hw][c]  8 MB
__device__ float g_juncs[TOPK * 2];               // x,y per junction
__device__ float g_feats[NLINES * DIM_FC];        // 80 MB
__device__ float g_h1[NLINES * DIM_FC];           // 80 MB
__device__ float g_h2[NLINES * DIM_FC];           // 80 MB

// ---------------- kernel 1: NMS + bitonic top-k + junction decode ----------
// one block, 1024 threads, 128 KB dynamic smem for 16384 64-bit keys
__global__ void topk_juncs_kernel(const float* __restrict__ jloc,
                                  const float* __restrict__ joff) {
    extern __shared__ unsigned long long keys[];
    const int n = NPIX;
    int tid = threadIdx.x;

    for (int i = tid; i < n; i += 1024) {
        int y = i >> 7, x = i & 127;
        float v = jloc[i];
        float m = v;
        #pragma unroll
        for (int dy = -1; dy <= 1; dy++)
            #pragma unroll
            for (int dx = -1; dx <= 1; dx++) {
                int yy = y + dy, xx = x + dx;
                if (yy >= 0 && yy < HW && xx >= 0 && xx < HW)
                    m = fmaxf(m, jloc[yy * HW + xx]);
            }
        float nmsv = (v == m) ? v : 0.0f;   // jloc >= 0 so float bits are order-preserving
        keys[i] = ((unsigned long long)__float_as_uint(nmsv) << 32)
                | (unsigned long long)(0xFFFFFFFFu - (unsigned)i);  // tie: lower idx wins
    }
    __syncthreads();

    // bitonic sort, descending
    for (int k = 2; k <= n; k <<= 1) {
        for (int j = k >> 1; j > 0; j >>= 1) {
            for (int i = tid; i < n; i += 1024) {
                int ixj = i ^ j;
                if (ixj > i) {
                    unsigned long long a = keys[i], b = keys[ixj];
                    bool up = ((i & k) == 0);
                    if ((a < b) == up) { keys[i] = b; keys[ixj] = a; }
                }
            }
            __syncthreads();
        }
    }

    if (tid < TOPK) {
        unsigned long long key = keys[tid];
        unsigned idx = 0xFFFFFFFFu - (unsigned)(key & 0xFFFFFFFFull);
        // x = col + sigmoid(joff0); y = row + sigmoid(joff1)   (the -0.5 and +0.5 cancel)
        float j0 = joff[idx];
        float j1 = joff[NPIX + idx];
        float sx = 1.0f / (1.0f + expf(-j0));
        float sy = 1.0f / (1.0f + expf(-j1));
        g_juncs[2 * tid + 0] = (float)(idx & 127) + sx;
        g_juncs[2 * tid + 1] = (float)(idx >> 7) + sy;
    }
}

// ---------------- kernel 2: transpose loi [C][HW] -> [HW][C] ---------------
__global__ void transpose_loi_kernel(const float* __restrict__ in) {
    __shared__ float tile[32][33];
    int p0 = blockIdx.x * 32;   // pixel block
    int c0 = blockIdx.y * 32;   // channel block
    int tx = threadIdx.x, ty = threadIdx.y;   // 32 x 8
    #pragma unroll
    for (int i = 0; i < 32; i += 8)
        tile[ty + i][tx] = in[(size_t)(c0 + ty + i) * NPIX + p0 + tx];
    __syncthreads();
    #pragma unroll
    for (int i = 0; i < 32; i += 8)
        g_loiT[(size_t)(p0 + ty + i) * DIM_LOI + c0 + tx] = tile[tx][ty + i];
}

// ---------------- kernel 3: line sampling + bilinear + group max -----------
// one block (128 threads = channels) per line
__global__ void sample_kernel(const int* __restrict__ edge) {
    __shared__ int   s_off[NPTS0][4];
    __shared__ float s_w[NPTS0][4];
    __shared__ float s_out[DIM_FC];

    int n = blockIdx.x;
    int tid = threadIdx.x;

    int e0 = edge[2 * n + 0];
    int e1 = edge[2 * n + 1];
    float Ux = g_juncs[2 * e0 + 0], Uy = g_juncs[2 * e0 + 1];
    float Vx = g_juncs[2 * e1 + 0], Vy = g_juncs[2 * e1 + 1];

    if (tid < NPTS0) {
        float t = (float)tid * (1.0f / 31.0f);
        float px = Ux * t + Vx * (1.0f - t) - 0.5f;
        float py = Uy * t + Vy * (1.0f - t) - 0.5f;
        float x0 = fminf(fmaxf(floorf(px), 0.0f), 127.0f);
        float y0 = fminf(fmaxf(floorf(py), 0.0f), 127.0f);
        float x1 = fminf(x0 + 1.0f, 127.0f);
        float y1 = fminf(y0 + 1.0f, 127.0f);
        int ix0 = (int)x0, iy0 = (int)y0, ix1 = (int)x1, iy1 = (int)y1;
        s_off[tid][0] = (iy0 * HW + ix0) * DIM_LOI;
        s_off[tid][1] = (iy1 * HW + ix0) * DIM_LOI;
        s_off[tid][2] = (iy0 * HW + ix1) * DIM_LOI;
        s_off[tid][3] = (iy1 * HW + ix1) * DIM_LOI;
        s_w[tid][0] = (y1 - py) * (x1 - px);
        s_w[tid][1] = (py - y0) * (x1 - px);
        s_w[tid][2] = (y1 - py) * (px - x0);
        s_w[tid][3] = (py - y0) * (px - x0);
    }
    __syncthreads();

    #pragma unroll
    for (int j = 0; j < NPTS1; j++) {
        float m = -__int_as_float(0x7f800000);  // -inf
        #pragma unroll
        for (int k = 0; k < 4; k++) {
            int p = j * 4 + k;
            float v = s_w[p][0] * g_loiT[s_off[p][0] + tid]
                    + s_w[p][1] * g_loiT[s_off[p][1] + tid]
                    + s_w[p][2] * g_loiT[s_off[p][2] + tid]
                    + s_w[p][3] * g_loiT[s_off[p][3] + tid];
            m = fmaxf(m, v);
        }
        s_out[tid * NPTS1 + j] = m;
    }
    __syncthreads();
    for (int i = tid; i < DIM_FC; i += 128)
        g_feats[(size_t)n * DIM_FC + i] = s_out[i];
}

// ---------------- kernel 4: SGEMM 128x128x8, double-buffered, fp32 ---------
// C[M,1024] = relu?(A[M,1024] @ B[1024,1024] + bias)
template <bool RELU>
__global__ __launch_bounds__(256, 2)
void sgemm_kernel(const float* __restrict__ A, const float* __restrict__ B,
                  const float* __restrict__ bias, float* __restrict__ C, int M) {
    const int K = 1024, N = 1024;
    __shared__ float As[2][8][128];
    __shared__ float Bs[2][8][128];

    int tid = threadIdx.x;
    int bm = blockIdx.y * 128;
    int bn = blockIdx.x * 128;

    int arow = tid >> 1;            // 0..127
    int acol = (tid & 1) * 4;       // 0 or 4
    int brow = tid >> 5;            // 0..7
    int bcol = (tid & 31) * 4;      // 0..124
    int tx = (tid & 15) * 8;
    int ty = (tid >> 4) * 8;

    float acc[8][8];
    #pragma unroll
    for (int i = 0; i < 8; i++)
        #pragma unroll
        for (int j = 0; j < 8; j++) acc[i][j] = 0.0f;

    // prologue: tile 0
    float4 a4 = make_float4(0.f, 0.f, 0.f, 0.f);
    if (bm + arow < M) a4 = *(const float4*)(A + (size_t)(bm + arow) * K + acol);
    float4 b4 = *(const float4*)(B + (size_t)brow * N + bn + bcol);
    As[0][acol + 0][arow] = a4.x; As[0][acol + 1][arow] = a4.y;
    As[0][acol + 2][arow] = a4.z; As[0][acol + 3][arow] = a4.w;
    *(float4*)&Bs[0][brow][bcol] = b4;
    __syncthreads();

    int cur = 0;
    for (int kt = 0; kt < K / 8; ++kt) {
        int nk = (kt + 1) * 8;
        bool has_next = nk < K;
        float4 a4n, b4n;
        if (has_next) {
            a4n = make_float4(0.f, 0.f, 0.f, 0.f);
            if (bm + arow < M) a4n = *(const float4*)(A + (size_t)(bm + arow) * K + nk + acol);
            b4n = *(const float4*)(B + (size_t)(nk + brow) * N + bn + bcol);
        }
        #pragma unroll
        for (int k = 0; k < 8; ++k) {
            float ar[8], br[8];
            #pragma unroll
            for (int i = 0; i < 8; i++) ar[i] = As[cur][k][ty + i];
            #pragma unroll
            for (int j = 0; j < 8; j++) br[j] = Bs[cur][k][tx + j];
            #pragma unroll
            for (int i = 0; i < 8; i++)
                #pragma unroll
                for (int j = 0; j < 8; j++)
                    acc[i][j] = fmaf(ar[i], br[j], acc[i][j]);
        }
        if (has_next) {
            int nb = cur ^ 1;
            As[nb][acol + 0][arow] = a4n.x; As[nb][acol + 1][arow] = a4n.y;
            As[nb][acol + 2][arow] = a4n.z; As[nb][acol + 3][arow] = a4n.w;
            *(float4*)&Bs[nb][brow][bcol] = b4n;
        }
        __syncthreads();
        cur ^= 1;
    }

    #pragma unroll
    for (int i = 0; i < 8; i++) {
        int r = bm + ty + i;
        if (r < M) {
            #pragma unroll
            for (int j = 0; j < 8; j++) {
                float v = acc[i][j] + bias[bn + tx + j];
                if (RELU) v = fmaxf(v, 0.0f);
                C[(size_t)r * N + bn + tx + j] = v;
            }
        }
    }
}

// ---------------- kernel 5: final 1024 -> 3 projection ---------------------
// one warp per row
__global__ void gemm3_kernel(const float* __restrict__ W3, const float* __restrict__ b3,
                             float* __restrict__ out) {
    __shared__ float sW[DIM_FC * NLAB];
    int tid = threadIdx.x;
    for (int i = tid; i < DIM_FC * NLAB; i += 256) sW[i] = W3[i];
    __syncthreads();

    int warp = tid >> 5;
    int lane = tid & 31;
    int r = blockIdx.x * 8 + warp;
    if (r >= NLINES) return;

    float a0 = 0.f, a1 = 0.f, a2 = 0.f;
    const float* hrow = g_h2 + (size_t)r * DIM_FC;
    for (int k = lane; k < DIM_FC; k += 32) {
        float h = hrow[k];
        a0 = fmaf(h, sW[k * 3 + 0], a0);
        a1 = fmaf(h, sW[k * 3 + 1], a1);
        a2 = fmaf(h, sW[k * 3 + 2], a2);
    }
    #pragma unroll
    for (int off = 16; off > 0; off >>= 1) {
        a0 += __shfl_down_sync(0xFFFFFFFFu, a0, off);
        a1 += __shfl_down_sync(0xFFFFFFFFu, a1, off);
        a2 += __shfl_down_sync(0xFFFFFFFFu, a2, off);
    }
    if (lane == 0) {
        out[r * 3 + 0] = a0 + b3[0];
        out[r * 3 + 1] = a1 + b3[1];
        out[r * 3 + 2] = a2 + b3[2];
    }
}

// ---------------- launch -----------------------------------------------------
extern "C" void kernel_launch(void* const* d_in, const int* in_sizes, int n_in,
                              void* d_out, int out_size) {
    const float* jloc = (const float*)d_in[0];
    const float* joff = (const float*)d_in[1];
    const float* loi  = (const float*)d_in[2];
    const int*   edge = (const int*)d_in[3];
    const float* W1   = (const float*)d_in[4];
    const float* b1   = (const float*)d_in[5];
    const float* W2   = (const float*)d_in[6];
    const float* b2   = (const float*)d_in[7];
    const float* W3   = (const float*)d_in[8];
    const float* b3   = (const float*)d_in[9];
    float* out = (float*)d_out;

    cudaFuncSetAttribute(topk_juncs_kernel,
                         cudaFuncAttributeMaxDynamicSharedMemorySize,
                         NPIX * sizeof(unsigned long long));

    // device scratch pointers
    float *feats, *h1, *h2;
    cudaGetSymbolAddress((void**)&feats, g_feats);
    cudaGetSymbolAddress((void**)&h1, g_h1);
    cudaGetSymbolAddress((void**)&h2, g_h2);

    topk_juncs_kernel<<<1, 1024, NPIX * sizeof(unsigned long long)>>>(jloc, joff);
    transpose_loi_kernel<<<dim3(NPIX / 32, DIM_LOI / 32), dim3(32, 8)>>>(loi);
    sample_kernel<<<NLINES, 128>>>(edge);

    dim3 gemm_grid(DIM_FC / 128, (NLINES + 127) / 128);
    sgemm_kernel<true><<<gemm_grid, 256>>>(feats, W1, b1, h1, NLINES);
    sgemm_kernel<true><<<gemm_grid, 256>>>(h1, W2, b2, h2, NLINES);

    gemm3_kernel<<<(NLINES + 7) / 8, 256>>>(W3, b3, out);
}

// round 5
// speedup vs baseline: 1.6675x; 1.6675x over previous
#include <cuda_runtime.h>
#include <cuda_bf16.h>
#include <math.h>
#include <cstdint>

#define HW 128
#define NPIX (HW*HW)          // 16384
#define TOPK 300
#define NLINES 20000
#define DIM_LOI 128
#define NPTS0 32
#define NPTS1 8
#define DIM_FC 1024
#define NLAB 3

// ---------------- scratch (device globals; no allocation allowed) ----------
__device__ float g_loiT[NPIX * DIM_LOI];          // [hw][c]  8 MB
__device__ float g_juncs[TOPK * 2];               // x,y per junction
__device__ float g_feats[NLINES * DIM_FC];        // 80 MB
__device__ float g_h1[NLINES * DIM_FC];           // 80 MB
__device__ float g_h2[NLINES * DIM_FC];           // 80 MB
__device__ float g_w1T[DIM_FC * DIM_FC];          // W1^T [N][K] 4 MB
__device__ float g_w2T[DIM_FC * DIM_FC];          // W2^T [N][K] 4 MB

// ======================= PTX helpers (arch-portable) ========================
__device__ __forceinline__ uint32_t smem_u32(const void* p) {
    uint32_t a;
    asm("{ .reg .u64 t; cvta.to.shared.u64 t, %1; cvt.u32.u64 %0, t; }" : "=r"(a) : "l"(p));
    return a;
}
#define CP_ASYNC16(sm, g) \
    asm volatile("cp.async.cg.shared.global [%0], [%1], 16;" :: "r"(sm), "l"(g) : "memory")
#define CP_COMMIT() asm volatile("cp.async.commit_group;" ::: "memory")
#define CP_WAIT(n)  asm volatile("cp.async.wait_group %0;" :: "n"(n) : "memory")

__device__ __forceinline__ uint32_t f2tf32(float x) {
    uint32_t r;
    asm("cvt.rna.tf32.f32 %0, %1;" : "=r"(r) : "f"(x));
    return r;
}
__device__ __forceinline__ void mma_tf32(float* c,
                                         uint32_t a0, uint32_t a1, uint32_t a2, uint32_t a3,
                                         uint32_t b0, uint32_t b1) {
    asm volatile(
        "mma.sync.aligned.m16n8k8.row.col.f32.tf32.tf32.f32 "
        "{%0,%1,%2,%3}, {%4,%5,%6,%7}, {%8,%9}, {%0,%1,%2,%3};"
        : "+f"(c[0]), "+f"(c[1]), "+f"(c[2]), "+f"(c[3])
        : "r"(a0), "r"(a1), "r"(a2), "r"(a3), "r"(b0), "r"(b1));
}

// ---------------- kernel 1: NMS + bitonic top-k + junction decode ----------
__global__ void topk_juncs_kernel(const float* __restrict__ jloc,
                                  const float* __restrict__ joff) {
    extern __shared__ unsigned long long keys[];
    const int n = NPIX;
    int tid = threadIdx.x;

    for (int i = tid; i < n; i += 1024) {
        int y = i >> 7, x = i & 127;
        float v = jloc[i];
        float m = v;
        #pragma unroll
        for (int dy = -1; dy <= 1; dy++)
            #pragma unroll
            for (int dx = -1; dx <= 1; dx++) {
                int yy = y + dy, xx = x + dx;
                if (yy >= 0 && yy < HW && xx >= 0 && xx < HW)
                    m = fmaxf(m, jloc[yy * HW + xx]);
            }
        float nmsv = (v == m) ? v : 0.0f;
        keys[i] = ((unsigned long long)__float_as_uint(nmsv) << 32)
                | (unsigned long long)(0xFFFFFFFFu - (unsigned)i);
    }
    __syncthreads();

    for (int k = 2; k <= n; k <<= 1) {
        for (int j = k >> 1; j > 0; j >>= 1) {
            for (int i = tid; i < n; i += 1024) {
                int ixj = i ^ j;
                if (ixj > i) {
                    unsigned long long a = keys[i], b = keys[ixj];
                    bool up = ((i & k) == 0);
                    if ((a < b) == up) { keys[i] = b; keys[ixj] = a; }
                }
            }
            __syncthreads();
        }
    }

    if (tid < TOPK) {
        unsigned long long key = keys[tid];
        unsigned idx = 0xFFFFFFFFu - (unsigned)(key & 0xFFFFFFFFull);
        float j0 = joff[idx];
        float j1 = joff[NPIX + idx];
        float sx = 1.0f / (1.0f + expf(-j0));
        float sy = 1.0f / (1.0f + expf(-j1));
        g_juncs[2 * tid + 0] = (float)(idx & 127) + sx;
        g_juncs[2 * tid + 1] = (float)(idx >> 7) + sy;
    }
}

// ---------------- kernel 2a: transpose loi [C][HW*HW] -> [HW*HW][C] --------
__global__ void transpose_loi_kernel(const float* __restrict__ in) {
    __shared__ float tile[32][33];
    int p0 = blockIdx.x * 32;
    int c0 = blockIdx.y * 32;
    int tx = threadIdx.x, ty = threadIdx.y;   // 32 x 8
    #pragma unroll
    for (int i = 0; i < 32; i += 8)
        tile[ty + i][tx] = in[(size_t)(c0 + ty + i) * NPIX + p0 + tx];
    __syncthreads();
    #pragma unroll
    for (int i = 0; i < 32; i += 8)
        g_loiT[(size_t)(p0 + ty + i) * DIM_LOI + c0 + tx] = tile[tx][ty + i];
}

// ---------------- kernel 2b: transpose 1024x1024 (W -> W^T, [N][K]) --------
__global__ void transpose1024_kernel(const float* __restrict__ in, float* __restrict__ out) {
    __shared__ float tile[32][33];
    int p0 = blockIdx.x * 32;
    int c0 = blockIdx.y * 32;
    int tx = threadIdx.x, ty = threadIdx.y;   // 32 x 8
    #pragma unroll
    for (int i = 0; i < 32; i += 8)
        tile[ty + i][tx] = in[(size_t)(c0 + ty + i) * DIM_FC + p0 + tx];
    __syncthreads();
    #pragma unroll
    for (int i = 0; i < 32; i += 8)
        out[(size_t)(p0 + ty + i) * DIM_FC + c0 + tx] = tile[tx][ty + i];
}

// ---------------- kernel 3: line sampling + bilinear + group max -----------
__global__ void sample_kernel(const int* __restrict__ edge) {
    __shared__ int   s_off[NPTS0][4];
    __shared__ float s_w[NPTS0][4];
    __shared__ float s_out[DIM_FC];

    int n = blockIdx.x;
    int tid = threadIdx.x;

    int e0 = edge[2 * n + 0];
    int e1 = edge[2 * n + 1];
    float Ux = g_juncs[2 * e0 + 0], Uy = g_juncs[2 * e0 + 1];
    float Vx = g_juncs[2 * e1 + 0], Vy = g_juncs[2 * e1 + 1];

    if (tid < NPTS0) {
        float t = (float)tid * (1.0f / 31.0f);
        float px = Ux * t + Vx * (1.0f - t) - 0.5f;
        float py = Uy * t + Vy * (1.0f - t) - 0.5f;
        float x0 = fminf(fmaxf(floorf(px), 0.0f), 127.0f);
        float y0 = fminf(fmaxf(floorf(py), 0.0f), 127.0f);
        float x1 = fminf(x0 + 1.0f, 127.0f);
        float y1 = fminf(y0 + 1.0f, 127.0f);
        int ix0 = (int)x0, iy0 = (int)y0, ix1 = (int)x1, iy1 = (int)y1;
        s_off[tid][0] = (iy0 * HW + ix0) * DIM_LOI;
        s_off[tid][1] = (iy1 * HW + ix0) * DIM_LOI;
        s_off[tid][2] = (iy0 * HW + ix1) * DIM_LOI;
        s_off[tid][3] = (iy1 * HW + ix1) * DIM_LOI;
        s_w[tid][0] = (y1 - py) * (x1 - px);
        s_w[tid][1] = (py - y0) * (x1 - px);
        s_w[tid][2] = (y1 - py) * (px - x0);
        s_w[tid][3] = (py - y0) * (px - x0);
    }
    __syncthreads();

    #pragma unroll
    for (int j = 0; j < NPTS1; j++) {
        float m = -__int_as_float(0x7f800000);
        #pragma unroll
        for (int k = 0; k < 4; k++) {
            int p = j * 4 + k;
            float v = s_w[p][0] * g_loiT[s_off[p][0] + tid]
                    + s_w[p][1] * g_loiT[s_off[p][1] + tid]
                    + s_w[p][2] * g_loiT[s_off[p][2] + tid]
                    + s_w[p][3] * g_loiT[s_off[p][3] + tid];
            m = fmaxf(m, v);
        }
        s_out[tid * NPTS1 + j] = m;
    }
    __syncthreads();
    for (int i = tid; i < DIM_FC; i += 128)
        g_feats[(size_t)n * DIM_FC + i] = s_out[i];
}

// ---------------- kernel 4: tf32 mma.sync GEMM, 128x128x32 tile ------------
// C[M,1024] = relu(A[M,1024] @ BT[1024,1024]^T + bias), BT is [N][K] K-major.
#define BK 32
#define NKT (DIM_FC / BK)            // 32
#define APAD 4
#define LDA (BK + APAD)              // 36 floats per row (144 B, 16B-aligned)
#define TILE_FLOATS (128 * LDA)      // 4608 floats per matrix per stage
#define STAGE_FLOATS (2 * TILE_FLOATS)

__global__ __launch_bounds__(256, 2)
void tc_gemm_kernel(const float* __restrict__ A, const float* __restrict__ BT,
                    const float* __restrict__ bias, float* __restrict__ C, int M)
{
    extern __shared__ float smem[];   // [2 stages][As 4608 | Bs 4608]
    const uint32_t sbase = smem_u32(smem);
    const int tid = threadIdx.x;
    const int lane = tid & 31;
    const int warp = tid >> 5;
    const int wm = warp & 1;          // 0..1 -> 64-row slab
    const int wn = warp >> 1;         // 0..3 -> 32-col slab
    const int bn = blockIdx.x * 128;
    const int bm = blockIdx.y * 128;

    // ---- global load addressing: each thread moves 4 float4 per matrix
    const int lrow = tid >> 3;        // 0..31, +32*i
    const int lcol = (tid & 7) * 4;   // float index within 32-wide k tile

    const float* gA[4];
    const float* gB[4];
    uint32_t sA[4], sB[4];
    #pragma unroll
    for (int i = 0; i < 4; i++) {
        int row = lrow + 32 * i;
        int ar = bm + row; if (ar >= M) ar = M - 1;     // clamp (rows never stored)
        gA[i] = A  + (size_t)ar * DIM_FC + lcol;
        gB[i] = BT + (size_t)(bn + row) * DIM_FC + lcol;
        sA[i] = sbase + (row * LDA + lcol) * 4;
        sB[i] = sbase + (TILE_FLOATS + row * LDA + lcol) * 4;
    }

    float acc[4][4][4];
    #pragma unroll
    for (int mf = 0; mf < 4; mf++)
        #pragma unroll
        for (int nf = 0; nf < 4; nf++)
            #pragma unroll
            for (int q = 0; q < 4; q++) acc[mf][nf][q] = 0.0f;

    // ---- prologue: stage 0 <- tile 0
    #pragma unroll
    for (int i = 0; i < 4; i++) { CP_ASYNC16(sA[i], gA[i]); CP_ASYNC16(sB[i], gB[i]); }
    CP_COMMIT();

    const int r0 = lane >> 2;         // 0..7
    const int c0 = lane & 3;          // 0..3

    for (int kt = 0; kt < NKT; kt++) {
        int stage = kt & 1;
        if (kt + 1 < NKT) {
            int ns = (kt + 1) & 1;
            uint32_t soff = ns * STAGE_FLOATS * 4;
            int goff = (kt + 1) * BK;
            #pragma unroll
            for (int i = 0; i < 4; i++) {
                CP_ASYNC16(sA[i] + soff, gA[i] + goff);
                CP_ASYNC16(sB[i] + soff, gB[i] + goff);
            }
            CP_COMMIT();
            CP_WAIT(1);
        } else {
            CP_WAIT(0);
        }
        __syncthreads();

        const float* As = smem + stage * STAGE_FLOATS;
        const float* Bs = As + TILE_FLOATS;

        #pragma unroll
        for (int kf = 0; kf < 4; kf++) {
            uint32_t a[4][4];
            #pragma unroll
            for (int mf = 0; mf < 4; mf++) {
                const float* ap = As + (wm * 64 + mf * 16 + r0) * LDA + kf * 8 + c0;
                a[mf][0] = f2tf32(ap[0]);
                a[mf][1] = f2tf32(ap[8 * LDA]);
                a[mf][2] = f2tf32(ap[4]);
                a[mf][3] = f2tf32(ap[8 * LDA + 4]);
            }
            uint32_t b[4][2];
            #pragma unroll
            for (int nf = 0; nf < 4; nf++) {
                const float* bp = Bs + (wn * 32 + nf * 8 + r0) * LDA + kf * 8 + c0;
                b[nf][0] = f2tf32(bp[0]);
                b[nf][1] = f2tf32(bp[4]);
            }
            #pragma unroll
            for (int mf = 0; mf < 4; mf++)
                #pragma unroll
                for (int nf = 0; nf < 4; nf++)
                    mma_tf32(acc[mf][nf], a[mf][0], a[mf][1], a[mf][2], a[mf][3],
                             b[nf][0], b[nf][1]);
        }
        __syncthreads();
    }

    // ---- epilogue: bias + relu + store (accum quad layout)
    #pragma unroll
    for (int mf = 0; mf < 4; mf++) {
        int row = bm + wm * 64 + mf * 16 + r0;
        #pragma unroll
        for (int nf = 0; nf < 4; nf++) {
            int col = bn + wn * 32 + nf * 8 + c0 * 2;
            float bx = bias[col], by = bias[col + 1];
            if (row < M) {
                float2 v;
                v.x = fmaxf(acc[mf][nf][0] + bx, 0.0f);
                v.y = fmaxf(acc[mf][nf][1] + by, 0.0f);
                *(float2*)(C + (size_t)row * DIM_FC + col) = v;
            }
            if (row + 8 < M) {
                float2 v;
                v.x = fmaxf(acc[mf][nf][2] + bx, 0.0f);
                v.y = fmaxf(acc[mf][nf][3] + by, 0.0f);
                *(float2*)(C + (size_t)(row + 8) * DIM_FC + col) = v;
            }
        }
    }
}

// ---------------- kernel 5: final 1024 -> 3 projection ---------------------
__global__ void gemm3_kernel(const float* __restrict__ W3, const float* __restrict__ b3,
                             float* __restrict__ out) {
    __shared__ float sW[DIM_FC * NLAB];
    int tid = threadIdx.x;
    for (int i = tid; i < DIM_FC * NLAB; i += 256) sW[i] = W3[i];
    __syncthreads();

    int warp = tid >> 5;
    int lane = tid & 31;
    int r = blockIdx.x * 8 + warp;
    if (r >= NLINES) return;

    float a0 = 0.f, a1 = 0.f, a2 = 0.f;
    const float* hrow = g_h2 + (size_t)r * DIM_FC;
    for (int k = lane; k < DIM_FC; k += 32) {
        float h = hrow[k];
        a0 = fmaf(h, sW[k * 3 + 0], a0);
        a1 = fmaf(h, sW[k * 3 + 1], a1);
        a2 = fmaf(h, sW[k * 3 + 2], a2);
    }
    #pragma unroll
    for (int off = 16; off > 0; off >>= 1) {
        a0 += __shfl_down_sync(0xFFFFFFFFu, a0, off);
        a1 += __shfl_down_sync(0xFFFFFFFFu, a1, off);
        a2 += __shfl_down_sync(0xFFFFFFFFu, a2, off);
    }
    if (lane == 0) {
        out[r * 3 + 0] = a0 + b3[0];
        out[r * 3 + 1] = a1 + b3[1];
        out[r * 3 + 2] = a2 + b3[2];
    }
}

// ---------------- launch ---------------------------------------------------
extern "C" void kernel_launch(void* const* d_in, const int* in_sizes, int n_in,
                              void* d_out, int out_size) {
    const float* jloc = (const float*)d_in[0];
    const float* joff = (const float*)d_in[1];
    const float* loi  = (const float*)d_in[2];
    const int*   edge = (const int*)d_in[3];
    const float* W1   = (const float*)d_in[4];
    const float* b1   = (const float*)d_in[5];
    const float* W2   = (const float*)d_in[6];
    const float* b2   = (const float*)d_in[7];
    const float* W3   = (const float*)d_in[8];
    const float* b3   = (const float*)d_in[9];
    float* out = (float*)d_out;

    cudaFuncSetAttribute(topk_juncs_kernel,
                         cudaFuncAttributeMaxDynamicSharedMemorySize,
                         NPIX * sizeof(unsigned long long));
    const int GEMM_SMEM = 2 * STAGE_FLOATS * sizeof(float);   // 73728 B
    cudaFuncSetAttribute(tc_gemm_kernel,
                         cudaFuncAttributeMaxDynamicSharedMemorySize, GEMM_SMEM);

    float *feats, *h1, *h2, *w1T, *w2T;
    cudaGetSymbolAddress((void**)&feats, g_feats);
    cudaGetSymbolAddress((void**)&h1, g_h1);
    cudaGetSymbolAddress((void**)&h2, g_h2);
    cudaGetSymbolAddress((void**)&w1T, g_w1T);
    cudaGetSymbolAddress((void**)&w2T, g_w2T);

    topk_juncs_kernel<<<1, 1024, NPIX * sizeof(unsigned long long)>>>(jloc, joff);
    transpose_loi_kernel<<<dim3(NPIX / 32, DIM_LOI / 32), dim3(32, 8)>>>(loi);
    transpose1024_kernel<<<dim3(32, 32), dim3(32, 8)>>>(W1, w1T);
    transpose1024_kernel<<<dim3(32, 32), dim3(32, 8)>>>(W2, w2T);
    sample_kernel<<<NLINES, 128>>>(edge);

    dim3 ggrid(DIM_FC / 128, (NLINES + 127) / 128);
    tc_gemm_kernel<<<ggrid, 256, GEMM_SMEM>>>(feats, w1T, b1, h1, NLINES);
    tc_gemm_kernel<<<ggrid, 256, GEMM_SMEM>>>(h1, w2T, b2, h2, NLINES);

    gemm3_kernel<<<(NLINES + 7) / 8, 256>>>(W3, b3, out);
}

// round 7
// speedup vs baseline: 2.7233x; 1.6332x over previous
#include <cuda_runtime.h>
#include <cuda_bf16.h>
#include <math.h>
#include <cstdint>

#define HW 128
#define NPIX (HW*HW)          // 16384
#define TOPK 300
#define NLINES 20000
#define DIM_LOI 128
#define NPTS0 32
#define NPTS1 8
#define DIM_FC 1024
#define NLAB 3

// permutation of k within each 32-block: s(k) = (k&3)*8 + (k>>2)
__host__ __device__ __forceinline__ int kperm(int k) { return ((k & 3) << 3) | (k >> 2); }

// ---------------- scratch (device globals; no allocation allowed) ----------
__device__ __align__(16) float g_loiT[NPIX * DIM_LOI];   // [hw][c]  8 MB
__device__ __align__(16) float g_juncs[TOPK * 2];
__device__ __align__(16) float g_feats[NLINES * DIM_FC]; // permuted+tf32
__device__ __align__(16) float g_h1[NLINES * DIM_FC];    // permuted+tf32
__device__ __align__(16) float g_h2[NLINES * DIM_FC];    // plain fp32
__device__ __align__(16) float g_w1T[DIM_FC * DIM_FC];   // W1^T [N][kperm] tf32
__device__ __align__(16) float g_w2T[DIM_FC * DIM_FC];   // W2^T [N][kperm] tf32

// ======================= PTX helpers (arch-portable) ========================
__device__ __forceinline__ uint32_t smem_u32(const void* p) {
    uint32_t a;
    asm("{ .reg .u64 t; cvta.to.shared.u64 t, %1; cvt.u32.u64 %0, t; }" : "=r"(a) : "l"(p));
    return a;
}
#define CP_ASYNC16(sm, g) \
    asm volatile("cp.async.cg.shared.global [%0], [%1], 16;" :: "r"(sm), "l"(g) : "memory")
#define CP_COMMIT() asm volatile("cp.async.commit_group;" ::: "memory")
#define CP_WAIT(n)  asm volatile("cp.async.wait_group %0;" :: "n"(n) : "memory")

__device__ __forceinline__ float f2tf32f(float x) {   // rna-round to tf32, as float
    uint32_t r;
    asm("cvt.rna.tf32.f32 %0, %1;" : "=r"(r) : "f"(x));
    return __uint_as_float(r);
}
__device__ __forceinline__ void mma_tf32(float* c,
                                         uint32_t a0, uint32_t a1, uint32_t a2, uint32_t a3,
                                         uint32_t b0, uint32_t b1) {
    asm volatile(
        "mma.sync.aligned.m16n8k8.row.col.f32.tf32.tf32.f32 "
        "{%0,%1,%2,%3}, {%4,%5,%6,%7}, {%8,%9}, {%0,%1,%2,%3};"
        : "+f"(c[0]), "+f"(c[1]), "+f"(c[2]), "+f"(c[3])
        : "r"(a0), "r"(a1), "r"(a2), "r"(a3), "r"(b0), "r"(b1));
}

// ---------------- kernel 1: NMS + compact + small bitonic top-k ------------
// one block, 1024 threads. NMS survivors of a 3x3 window are provably <= 4096.
#define SORTN 4096
__global__ void topk_juncs_kernel(const float* __restrict__ jloc,
                                  const float* __restrict__ joff) {
    __shared__ unsigned long long keys[SORTN];
    __shared__ int cnt;
    int tid = threadIdx.x;
    if (tid == 0) cnt = 0;
    #pragma unroll
    for (int i = tid; i < SORTN; i += 1024) keys[i] = 0ull;
    __syncthreads();

    for (int i = tid; i < NPIX; i += 1024) {
        int y = i >> 7, x = i & 127;
        float v = jloc[i];
        float m = v;
        #pragma unroll
        for (int dy = -1; dy <= 1; dy++)
            #pragma unroll
            for (int dx = -1; dx <= 1; dx++) {
                int yy = y + dy, xx = x + dx;
                if (yy >= 0 && yy < HW && xx >= 0 && xx < HW)
                    m = fmaxf(m, jloc[yy * HW + xx]);
            }
        if (v == m && v > 0.0f) {
            int p = atomicAdd(&cnt, 1);
            if (p < SORTN)
                keys[p] = ((unsigned long long)__float_as_uint(v) << 32)
                        | (unsigned long long)(0xFFFFFFFFu - (unsigned)i);
        }
    }
    __syncthreads();

    // bitonic sort SORTN descending (keys are unique; 0-padding sinks to the end)
    for (int k = 2; k <= SORTN; k <<= 1) {
        for (int j = k >> 1; j > 0; j >>= 1) {
            #pragma unroll
            for (int i = tid; i < SORTN; i += 1024) {
                int ixj = i ^ j;
                if (ixj > i) {
                    unsigned long long a = keys[i], b = keys[ixj];
                    bool up = ((i & k) == 0);
                    if ((a < b) == up) { keys[i] = b; keys[ixj] = a; }
                }
            }
            __syncthreads();
        }
    }

    if (tid < TOPK) {
        unsigned long long key = keys[tid];
        unsigned idx = 0xFFFFFFFFu - (unsigned)(key & 0xFFFFFFFFull);
        float j0 = joff[idx];
        float j1 = joff[NPIX + idx];
        float sx = 1.0f / (1.0f + expf(-j0));
        float sy = 1.0f / (1.0f + expf(-j1));
        g_juncs[2 * tid + 0] = (float)(idx & 127) + sx;   // x = col + sigmoid
        g_juncs[2 * tid + 1] = (float)(idx >> 7) + sy;    // y = row + sigmoid
    }
}

// ---------------- kernel 2a: transpose loi [C][HW*HW] -> [HW*HW][C] --------
__global__ void transpose_loi_kernel(const float* __restrict__ in) {
    __shared__ float tile[32][33];
    int p0 = blockIdx.x * 32;
    int c0 = blockIdx.y * 32;
    int tx = threadIdx.x, ty = threadIdx.y;   // 32 x 8
    #pragma unroll
    for (int i = 0; i < 32; i += 8)
        tile[ty + i][tx] = in[(size_t)(c0 + ty + i) * NPIX + p0 + tx];
    __syncthreads();
    #pragma unroll
    for (int i = 0; i < 32; i += 8)
        g_loiT[(size_t)(p0 + ty + i) * DIM_LOI + c0 + tx] = tile[tx][ty + i];
}

// ---------------- kernel 2b: W -> W^T with k-perm + tf32 rounding ----------
// in: [K=1024][N=1024] row-major; out: [N][kperm(K)] tf32-rounded
__global__ void transposeW_kernel(const float* __restrict__ in, float* __restrict__ out) {
    __shared__ float tile[32][33];
    int p0 = blockIdx.x * 32;   // n block
    int c0 = blockIdx.y * 32;   // k block
    int tx = threadIdx.x, ty = threadIdx.y;   // 32 x 8
    #pragma unroll
    for (int i = 0; i < 32; i += 8)
        tile[ty + i][tx] = in[(size_t)(c0 + ty + i) * DIM_FC + p0 + tx];
    __syncthreads();
    #pragma unroll
    for (int i = 0; i < 32; i += 8)
        out[(size_t)(p0 + ty + i) * DIM_FC + c0 + kperm(tx)] = f2tf32f(tile[tx][ty + i]);
}

// ---------------- kernel 3: line sampling + bilinear + group max -----------
// 128 threads: quad q=tid>>5 handles points [8q,8q+8), lane handles 4 channels.
__global__ void sample_kernel(const int* __restrict__ edge) {
    __shared__ int   s_off[NPTS0][4];
    __shared__ float s_w[NPTS0][4];
    __shared__ float s_out[DIM_FC];

    int n = blockIdx.x;
    int tid = threadIdx.x;
    int lane = tid & 31;
    int q = tid >> 5;

    if (tid < NPTS0) {
        int e0 = edge[2 * n + 0];
        int e1 = edge[2 * n + 1];
        float Ux = g_juncs[2 * e0 + 0], Uy = g_juncs[2 * e0 + 1];
        float Vx = g_juncs[2 * e1 + 0], Vy = g_juncs[2 * e1 + 1];
        float t = (float)tid * (1.0f / 31.0f);
        float px = Ux * t + Vx * (1.0f - t) - 0.5f;
        float py = Uy * t + Vy * (1.0f - t) - 0.5f;
        float x0 = fminf(fmaxf(floorf(px), 0.0f), 127.0f);
        float y0 = fminf(fmaxf(floorf(py), 0.0f), 127.0f);
        float x1 = fminf(x0 + 1.0f, 127.0f);
        float y1 = fminf(y0 + 1.0f, 127.0f);
        int ix0 = (int)x0, iy0 = (int)y0, ix1 = (int)x1, iy1 = (int)y1;
        s_off[tid][0] = (iy0 * HW + ix0) * DIM_LOI;
        s_off[tid][1] = (iy1 * HW + ix0) * DIM_LOI;
        s_off[tid][2] = (iy0 * HW + ix1) * DIM_LOI;
        s_off[tid][3] = (iy1 * HW + ix1) * DIM_LOI;
        s_w[tid][0] = (y1 - py) * (x1 - px);
        s_w[tid][1] = (py - y0) * (x1 - px);
        s_w[tid][2] = (y1 - py) * (px - x0);
        s_w[tid][3] = (py - y0) * (px - x0);
    }
    __syncthreads();

    const float4* loi4 = (const float4*)g_loiT;
    int cq = lane;   // channel quad: channels 4*lane .. 4*lane+3

    #pragma unroll
    for (int j2 = 0; j2 < 2; j2++) {
        int j = q * 2 + j2;       // maxpool group 0..7
        float4 m = make_float4(-1e30f, -1e30f, -1e30f, -1e30f);
        #pragma unroll
        for (int k = 0; k < 4; k++) {
            int p = j * 4 + k;
            float w0 = s_w[p][0], w1 = s_w[p][1], w2 = s_w[p][2], w3 = s_w[p][3];
            float4 v0 = loi4[(s_off[p][0] >> 2) + cq];
            float4 v1 = loi4[(s_off[p][1] >> 2) + cq];
            float4 v2 = loi4[(s_off[p][2] >> 2) + cq];
            float4 v3 = loi4[(s_off[p][3] >> 2) + cq];
            float4 v;
            v.x = w0 * v0.x + w1 * v1.x + w2 * v2.x + w3 * v3.x;
            v.y = w0 * v0.y + w1 * v1.y + w2 * v2.y + w3 * v3.y;
            v.z = w0 * v0.z + w1 * v1.z + w2 * v2.z + w3 * v3.z;
            v.w = w0 * v0.w + w1 * v1.w + w2 * v2.w + w3 * v3.w;
            m.x = fmaxf(m.x, v.x); m.y = fmaxf(m.y, v.y);
            m.z = fmaxf(m.z, v.z); m.w = fmaxf(m.w, v.w);
        }
        s_out[(cq * 4 + 0) * NPTS1 + j] = m.x;
        s_out[(cq * 4 + 1) * NPTS1 + j] = m.y;
        s_out[(cq * 4 + 2) * NPTS1 + j] = m.z;
        s_out[(cq * 4 + 3) * NPTS1 + j] = m.w;
    }
    __syncthreads();

    // store permuted + tf32-rounded (feeds GEMM1 A operand)
    for (int f = tid; f < DIM_FC; f += 128) {
        int pos = (f & ~31) | kperm(f & 31);
        g_feats[(size_t)n * DIM_FC + pos] = f2tf32f(s_out[f]);
    }
}

// ---------------- kernel 4: tf32 mma GEMM, 128x256 tile, 64x64 warp tile ---
// C[M,1024] = relu(A[M,1024] @ BT[1024,1024]^T + bias)
// A, BT already k-permuted + tf32-rounded. PERM_OUT: store C k-permuted+tf32.
#define BK 32
#define NKT (DIM_FC / BK)            // 32
#define APAD 4
#define LDA (BK + APAD)              // 36 floats
#define BM 128
#define BN 256
#define ATILE (BM * LDA)             // floats
#define BTILE (BN * LDA)
#define STAGE (ATILE + BTILE)        // 13824 floats

template <bool PERM_OUT>
__global__ __launch_bounds__(256, 1)
void tc_gemm_kernel(const float* __restrict__ A, const float* __restrict__ BT,
                    const float* __restrict__ bias, float* __restrict__ C, int M)
{
    extern __shared__ float smem[];   // [2 stages][A | B]
    __shared__ float sbias[BN];
    const uint32_t sbase = smem_u32(smem);
    const int tid = threadIdx.x;
    const int lane = tid & 31;
    const int warp = tid >> 5;
    const int wm = warp & 1;          // 2 row slabs of 64
    const int wn = warp >> 1;         // 4 col slabs of 64
    const int bn = blockIdx.x * BN;
    const int bm = blockIdx.y * BM;

    sbias[tid] = bias[bn + tid];

    // global->smem addressing: row = tid>>3 (+32*i), chunk = tid&7 (16B)
    const int lrow = tid >> 3;
    const int lchk = (tid & 7) * 4;

    const float* gA[4];
    uint32_t sA[4];
    #pragma unroll
    for (int i = 0; i < 4; i++) {
        int row = lrow + 32 * i;
        int ar = bm + row; if (ar >= M) ar = M - 1;
        gA[i] = A + (size_t)ar * DIM_FC + lchk;
        sA[i] = sbase + (row * LDA + lchk) * 4;
    }
    const float* gB[8];
    uint32_t sB[8];
    #pragma unroll
    for (int i = 0; i < 8; i++) {
        int row = lrow + 32 * i;
        gB[i] = BT + (size_t)(bn + row) * DIM_FC + lchk;
        sB[i] = sbase + (ATILE + row * LDA + lchk) * 4;
    }

    float acc[4][8][4];
    #pragma unroll
    for (int mf = 0; mf < 4; mf++)
        #pragma unroll
        for (int nf = 0; nf < 8; nf++)
            #pragma unroll
            for (int qq = 0; qq < 4; qq++) acc[mf][nf][qq] = 0.0f;

    // prologue: stage 0 <- ktile 0
    #pragma unroll
    for (int i = 0; i < 4; i++) CP_ASYNC16(sA[i], gA[i]);
    #pragma unroll
    for (int i = 0; i < 8; i++) CP_ASYNC16(sB[i], gB[i]);
    CP_COMMIT();

    const int g  = lane >> 2;         // 0..7
    const int c0 = lane & 3;          // 0..3

    for (int kt = 0; kt < NKT; kt++) {
        int stage = kt & 1;
        if (kt + 1 < NKT) {
            uint32_t soff = ((kt + 1) & 1) * STAGE * 4;
            int goff = (kt + 1) * BK;
            #pragma unroll
            for (int i = 0; i < 4; i++) CP_ASYNC16(sA[i] + soff, gA[i] + goff);
            #pragma unroll
            for (int i = 0; i < 8; i++) CP_ASYNC16(sB[i] + soff, gB[i] + goff);
            CP_COMMIT();
            CP_WAIT(1);
        } else {
            CP_WAIT(0);
        }
        __syncthreads();

        const float* As = smem + stage * STAGE;
        const float* Bs = As + ATILE;

        #pragma unroll
        for (int h = 0; h < 2; h++) {   // h covers kf {2h, 2h+1}
            float4 av[4][2];
            #pragma unroll
            for (int mf = 0; mf < 4; mf++) {
                const float* ap = As + (wm * 64 + mf * 16 + g) * LDA + c0 * 8 + 4 * h;
                av[mf][0] = *(const float4*)ap;
                av[mf][1] = *(const float4*)(ap + 8 * LDA);
            }
            float4 bv[8];
            #pragma unroll
            for (int nf = 0; nf < 8; nf++)
                bv[nf] = *(const float4*)(Bs + (wn * 64 + nf * 8 + g) * LDA + c0 * 8 + 4 * h);

            #pragma unroll
            for (int m2 = 0; m2 < 2; m2++) {   // kf = 2h + m2
                #pragma unroll
                for (int mf = 0; mf < 4; mf++) {
                    uint32_t a0 = __float_as_uint(m2 ? av[mf][0].z : av[mf][0].x);
                    uint32_t a2 = __float_as_uint(m2 ? av[mf][0].w : av[mf][0].y);
                    uint32_t a1 = __float_as_uint(m2 ? av[mf][1].z : av[mf][1].x);
                    uint32_t a3 = __float_as_uint(m2 ? av[mf][1].w : av[mf][1].y);
                    #pragma unroll
                    for (int nf = 0; nf < 8; nf++) {
                        uint32_t b0 = __float_as_uint(m2 ? bv[nf].z : bv[nf].x);
                        uint32_t b1 = __float_as_uint(m2 ? bv[nf].w : bv[nf].y);
                        mma_tf32(acc[mf][nf], a0, a1, a2, a3, b0, b1);
                    }
                }
            }
        }
        __syncthreads();
    }

    // epilogue: bias + relu (+ optional perm + tf32 round) + store
    #pragma unroll
    for (int mf = 0; mf < 4; mf++) {
        int row0 = bm + wm * 64 + mf * 16 + g;
        #pragma unroll
        for (int nf = 0; nf < 8; nf++) {
            int coll = wn * 64 + nf * 8 + c0 * 2;   // local col (pair)
            float bx = sbias[coll], by = sbias[coll + 1];
            #pragma unroll
            for (int half = 0; half < 2; half++) {
                int row = row0 + half * 8;
                if (row < M) {
                    float vx = fmaxf(acc[mf][nf][half * 2 + 0] + bx, 0.0f);
                    float vy = fmaxf(acc[mf][nf][half * 2 + 1] + by, 0.0f);
                    if (PERM_OUT) {
                        int cx = bn + coll, cy = cx + 1;
                        C[(size_t)row * DIM_FC + ((cx & ~31) | kperm(cx & 31))] = f2tf32f(vx);
                        C[(size_t)row * DIM_FC + ((cy & ~31) | kperm(cy & 31))] = f2tf32f(vy);
                    } else {
                        float2 v; v.x = vx; v.y = vy;
                        *(float2*)(C + (size_t)row * DIM_FC + bn + coll) = v;
                    }
                }
            }
        }
    }
}

// ---------------- kernel 5: final 1024 -> 3 projection ---------------------
__global__ void gemm3_kernel(const float* __restrict__ W3, const float* __restrict__ b3,
                             float* __restrict__ out) {
    __shared__ float sW[DIM_FC * NLAB];
    int tid = threadIdx.x;
    for (int i = tid; i < DIM_FC * NLAB; i += 256) sW[i] = W3[i];
    __syncthreads();

    int warp = tid >> 5;
    int lane = tid & 31;
    int r = blockIdx.x * 8 + warp;
    if (r >= NLINES) return;

    float a0 = 0.f, a1 = 0.f, a2 = 0.f;
    const float* hrow = g_h2 + (size_t)r * DIM_FC;
    for (int k = lane; k < DIM_FC; k += 32) {
        float h = hrow[k];
        a0 = fmaf(h, sW[k * 3 + 0], a0);
        a1 = fmaf(h, sW[k * 3 + 1], a1);
        a2 = fmaf(h, sW[k * 3 + 2], a2);
    }
    #pragma unroll
    for (int off = 16; off > 0; off >>= 1) {
        a0 += __shfl_down_sync(0xFFFFFFFFu, a0, off);
        a1 += __shfl_down_sync(0xFFFFFFFFu, a1, off);
        a2 += __shfl_down_sync(0xFFFFFFFFu, a2, off);
    }
    if (lane == 0) {
        out[r * 3 + 0] = a0 + b3[0];
        out[r * 3 + 1] = a1 + b3[1];
        out[r * 3 + 2] = a2 + b3[2];
    }
}

// ---------------- launch ---------------------------------------------------
extern "C" void kernel_launch(void* const* d_in, const int* in_sizes, int n_in,
                              void* d_out, int out_size) {
    const float* jloc = (const float*)d_in[0];
    const float* joff = (const float*)d_in[1];
    const float* loi  = (const float*)d_in[2];
    const int*   edge = (const int*)d_in[3];
    const float* W1   = (const float*)d_in[4];
    const float* b1   = (const float*)d_in[5];
    const float* W2   = (const float*)d_in[6];
    const float* b2   = (const float*)d_in[7];
    const float* W3   = (const float*)d_in[8];
    const float* b3   = (const float*)d_in[9];
    float* out = (float*)d_out;

    const int GEMM_SMEM = 2 * STAGE * sizeof(float);   // 110592 B
    cudaFuncSetAttribute(tc_gemm_kernel<true>,
                         cudaFuncAttributeMaxDynamicSharedMemorySize, GEMM_SMEM);
    cudaFuncSetAttribute(tc_gemm_kernel<false>,
                         cudaFuncAttributeMaxDynamicSharedMemorySize, GEMM_SMEM);

    float *feats, *h1, *h2, *w1T, *w2T;
    cudaGetSymbolAddress((void**)&feats, g_feats);
    cudaGetSymbolAddress((void**)&h1, g_h1);
    cudaGetSymbolAddress((void**)&h2, g_h2);
    cudaGetSymbolAddress((void**)&w1T, g_w1T);
    cudaGetSymbolAddress((void**)&w2T, g_w2T);

    topk_juncs_kernel<<<1, 1024>>>(jloc, joff);
    transpose_loi_kernel<<<dim3(NPIX / 32, DIM_LOI / 32), dim3(32, 8)>>>(loi);
    transposeW_kernel<<<dim3(32, 32), dim3(32, 8)>>>(W1, w1T);
    transposeW_kernel<<<dim3(32, 32), dim3(32, 8)>>>(W2, w2T);
    sample_kernel<<<NLINES, 128>>>(edge);

    dim3 ggrid(DIM_FC / BN, (NLINES + BM - 1) / BM);
    tc_gemm_kernel<true ><<<ggrid, 256, GEMM_SMEM>>>(feats, w1T, b1, h1, NLINES);
    tc_gemm_kernel<false><<<ggrid, 256, GEMM_SMEM>>>(h1, w2T, b2, h2, NLINES);

    gemm3_kernel<<<(NLINES + 7) / 8, 256>>>(W3, b3, out);
}

// round 8
// speedup vs baseline: 4.6629x; 1.7122x over previous
#include <cuda_runtime.h>
#include <cuda_fp16.h>
#include <math.h>
#include <cstdint>

#define HW 128
#define NPIX (HW*HW)          // 16384
#define TOPK 300
#define NLINES 20000
#define DIM_LOI 128
#define NPTS0 32
#define NPTS1 8
#define DIM_FC 1024
#define NLAB 3

// pair-permutation within a 32-k block (16 pairs): p' = (p&3)*4 + (p>>2)
// gives each (thread c0) its 4 needed pairs {c0, c0+4, c0+8, c0+12} contiguously.
__host__ __device__ __forceinline__ int khperm(int k) {
    int p = k >> 1;
    int pp = ((p & 3) << 2) | (p >> 2);
    return (pp << 1) | (k & 1);
}

// ---------------- scratch (device globals; no allocation allowed) ----------
__device__ __align__(16) float  g_loiT[NPIX * DIM_LOI];    // [hw][c]  8 MB
__device__ __align__(16) float  g_juncs[TOPK * 2];
__device__ __align__(16) __half g_feats[NLINES * DIM_FC];  // permuted fp16
__device__ __align__(16) __half g_h1[NLINES * DIM_FC];     // permuted fp16
__device__ __align__(16) float  g_h2[NLINES * DIM_FC];     // plain fp32
__device__ __align__(16) __half g_w1T[DIM_FC * DIM_FC];    // W1^T [N][kperm]
__device__ __align__(16) __half g_w2T[DIM_FC * DIM_FC];    // W2^T [N][kperm]

// ======================= PTX helpers ========================================
__device__ __forceinline__ uint32_t smem_u32(const void* p) {
    uint32_t a;
    asm("{ .reg .u64 t; cvta.to.shared.u64 t, %1; cvt.u32.u64 %0, t; }" : "=r"(a) : "l"(p));
    return a;
}
#define CP_ASYNC16(sm, g) \
    asm volatile("cp.async.cg.shared.global [%0], [%1], 16;" :: "r"(sm), "l"(g) : "memory")
#define CP_COMMIT() asm volatile("cp.async.commit_group;" ::: "memory")
#define CP_WAIT(n)  asm volatile("cp.async.wait_group %0;" :: "n"(n) : "memory")

__device__ __forceinline__ void mma_f16(float* c,
                                        uint32_t a0, uint32_t a1, uint32_t a2, uint32_t a3,
                                        uint32_t b0, uint32_t b1) {
    asm volatile(
        "mma.sync.aligned.m16n8k16.row.col.f32.f16.f16.f32 "
        "{%0,%1,%2,%3}, {%4,%5,%6,%7}, {%8,%9}, {%0,%1,%2,%3};"
        : "+f"(c[0]), "+f"(c[1]), "+f"(c[2]), "+f"(c[3])
        : "r"(a0), "r"(a1), "r"(a2), "r"(a3), "r"(b0), "r"(b1));
}

// ---------------- kernel 1: NMS + compact + small bitonic top-k ------------
#define SORTN 4096
__global__ void topk_juncs_kernel(const float* __restrict__ jloc,
                                  const float* __restrict__ joff) {
    __shared__ unsigned long long keys[SORTN];
    __shared__ int cnt;
    int tid = threadIdx.x;
    if (tid == 0) cnt = 0;
    #pragma unroll
    for (int i = tid; i < SORTN; i += 1024) keys[i] = 0ull;
    __syncthreads();

    for (int i = tid; i < NPIX; i += 1024) {
        int y = i >> 7, x = i & 127;
        float v = jloc[i];
        float m = v;
        #pragma unroll
        for (int dy = -1; dy <= 1; dy++)
            #pragma unroll
            for (int dx = -1; dx <= 1; dx++) {
                int yy = y + dy, xx = x + dx;
                if (yy >= 0 && yy < HW && xx >= 0 && xx < HW)
                    m = fmaxf(m, jloc[yy * HW + xx]);
            }
        if (v == m && v > 0.0f) {
            int p = atomicAdd(&cnt, 1);
            if (p < SORTN)
                keys[p] = ((unsigned long long)__float_as_uint(v) << 32)
                        | (unsigned long long)(0xFFFFFFFFu - (unsigned)i);
        }
    }
    __syncthreads();

    for (int k = 2; k <= SORTN; k <<= 1) {
        for (int j = k >> 1; j > 0; j >>= 1) {
            #pragma unroll
            for (int i = tid; i < SORTN; i += 1024) {
                int ixj = i ^ j;
                if (ixj > i) {
                    unsigned long long a = keys[i], b = keys[ixj];
                    bool up = ((i & k) == 0);
                    if ((a < b) == up) { keys[i] = b; keys[ixj] = a; }
                }
            }
            __syncthreads();
        }
    }

    if (tid < TOPK) {
        unsigned long long key = keys[tid];
        unsigned idx = 0xFFFFFFFFu - (unsigned)(key & 0xFFFFFFFFull);
        float j0 = joff[idx];
        float j1 = joff[NPIX + idx];
        float sx = 1.0f / (1.0f + expf(-j0));
        float sy = 1.0f / (1.0f + expf(-j1));
        g_juncs[2 * tid + 0] = (float)(idx & 127) + sx;
        g_juncs[2 * tid + 1] = (float)(idx >> 7) + sy;
    }
}

// ---------------- kernel 2a: transpose loi [C][HW*HW] -> [HW*HW][C] --------
__global__ void transpose_loi_kernel(const float* __restrict__ in) {
    __shared__ float tile[32][33];
    int p0 = blockIdx.x * 32;
    int c0 = blockIdx.y * 32;
    int tx = threadIdx.x, ty = threadIdx.y;   // 32 x 8
    #pragma unroll
    for (int i = 0; i < 32; i += 8)
        tile[ty + i][tx] = in[(size_t)(c0 + ty + i) * NPIX + p0 + tx];
    __syncthreads();
    #pragma unroll
    for (int i = 0; i < 32; i += 8)
        g_loiT[(size_t)(p0 + ty + i) * DIM_LOI + c0 + tx] = tile[tx][ty + i];
}

// ---------------- kernel 2b: W -> W^T with k-perm + fp16 -------------------
// in: [K=1024][N=1024]; out: [N][kperm(K)] fp16
__global__ void transposeW_kernel(const float* __restrict__ in, __half* __restrict__ out) {
    __shared__ float tile[32][33];
    int p0 = blockIdx.x * 32;   // n block
    int c0 = blockIdx.y * 32;   // k block
    int tx = threadIdx.x, ty = threadIdx.y;   // 32 x 8
    #pragma unroll
    for (int i = 0; i < 32; i += 8)
        tile[ty + i][tx] = in[(size_t)(c0 + ty + i) * DIM_FC + p0 + tx];
    __syncthreads();
    #pragma unroll
    for (int i = 0; i < 32; i += 8)
        out[(size_t)(p0 + ty + i) * DIM_FC + c0 + khperm(tx)] =
            __float2half_rn(tile[tx][ty + i]);
}

// ---------------- kernel 3: line sampling + bilinear + group max -----------
__global__ void sample_kernel(const int* __restrict__ edge) {
    __shared__ int   s_off[NPTS0][4];
    __shared__ float s_w[NPTS0][4];
    __shared__ float s_out[DIM_FC];

    int n = blockIdx.x;
    int tid = threadIdx.x;
    int lane = tid & 31;
    int q = tid >> 5;

    if (tid < NPTS0) {
        int e0 = edge[2 * n + 0];
        int e1 = edge[2 * n + 1];
        float Ux = g_juncs[2 * e0 + 0], Uy = g_juncs[2 * e0 + 1];
        float Vx = g_juncs[2 * e1 + 0], Vy = g_juncs[2 * e1 + 1];
        float t = (float)tid * (1.0f / 31.0f);
        float px = Ux * t + Vx * (1.0f - t) - 0.5f;
        float py = Uy * t + Vy * (1.0f - t) - 0.5f;
        float x0 = fminf(fmaxf(floorf(px), 0.0f), 127.0f);
        float y0 = fminf(fmaxf(floorf(py), 0.0f), 127.0f);
        float x1 = fminf(x0 + 1.0f, 127.0f);
        float y1 = fminf(y0 + 1.0f, 127.0f);
        int ix0 = (int)x0, iy0 = (int)y0, ix1 = (int)x1, iy1 = (int)y1;
        s_off[tid][0] = (iy0 * HW + ix0) * DIM_LOI;
        s_off[tid][1] = (iy1 * HW + ix0) * DIM_LOI;
        s_off[tid][2] = (iy0 * HW + ix1) * DIM_LOI;
        s_off[tid][3] = (iy1 * HW + ix1) * DIM_LOI;
        s_w[tid][0] = (y1 - py) * (x1 - px);
        s_w[tid][1] = (py - y0) * (x1 - px);
        s_w[tid][2] = (y1 - py) * (px - x0);
        s_w[tid][3] = (py - y0) * (px - x0);
    }
    __syncthreads();

    const float4* loi4 = (const float4*)g_loiT;
    int cq = lane;

    #pragma unroll
    for (int j2 = 0; j2 < 2; j2++) {
        int j = q * 2 + j2;
        float4 m = make_float4(-1e30f, -1e30f, -1e30f, -1e30f);
        #pragma unroll
        for (int k = 0; k < 4; k++) {
            int p = j * 4 + k;
            float w0 = s_w[p][0], w1 = s_w[p][1], w2 = s_w[p][2], w3 = s_w[p][3];
            float4 v0 = loi4[(s_off[p][0] >> 2) + cq];
            float4 v1 = loi4[(s_off[p][1] >> 2) + cq];
            float4 v2 = loi4[(s_off[p][2] >> 2) + cq];
            float4 v3 = loi4[(s_off[p][3] >> 2) + cq];
            float4 v;
            v.x = w0 * v0.x + w1 * v1.x + w2 * v2.x + w3 * v3.x;
            v.y = w0 * v0.y + w1 * v1.y + w2 * v2.y + w3 * v3.y;
            v.z = w0 * v0.z + w1 * v1.z + w2 * v2.z + w3 * v3.z;
            v.w = w0 * v0.w + w1 * v1.w + w2 * v2.w + w3 * v3.w;
            m.x = fmaxf(m.x, v.x); m.y = fmaxf(m.y, v.y);
            m.z = fmaxf(m.z, v.z); m.w = fmaxf(m.w, v.w);
        }
        s_out[(cq * 4 + 0) * NPTS1 + j] = m.x;
        s_out[(cq * 4 + 1) * NPTS1 + j] = m.y;
        s_out[(cq * 4 + 2) * NPTS1 + j] = m.z;
        s_out[(cq * 4 + 3) * NPTS1 + j] = m.w;
    }
    __syncthreads();

    // store permuted + fp16 (feeds GEMM1 A operand)
    for (int f = tid; f < DIM_FC; f += 128) {
        int pos = (f & ~31) | khperm(f & 31);
        g_feats[(size_t)n * DIM_FC + pos] = __float2half_rn(s_out[f]);
    }
}

// ---------------- kernel 4: fp16 mma GEMM, 128x256 tile, 64x64 warp tile ---
// C[M,1024] = relu(A[M,1024] @ BT[1024,1024]^T + bias)
// A, BT fp16 k-permuted. PERM_OUT: C is fp16 k-permuted; else fp32 plain.
#define BK 32                         // halves per k-tile (64 B per row)
#define NKT (DIM_FC / BK)             // 32
#define BM 128
#define BN 256
#define ATILE (BM * BK)               // halves (no padding; 64B rows tile banks)
#define BTILE (BN * BK)
#define STAGE (ATILE + BTILE)         // 12288 halves = 24 KB
#define NSTG 4

template <bool PERM_OUT>
__global__ __launch_bounds__(256, 1)
void hgemm_kernel(const __half* __restrict__ A, const __half* __restrict__ BT,
                  const float* __restrict__ bias, void* __restrict__ Cout, int M)
{
    extern __shared__ __half smem[];   // [NSTG][A | B]
    __shared__ float sbias[BN];
    const uint32_t sbase = smem_u32(smem);
    const int tid = threadIdx.x;
    const int lane = tid & 31;
    const int warp = tid >> 5;
    const int wm = warp & 1;           // 2 row slabs of 64
    const int wn = warp >> 1;          // 4 col slabs of 64
    const int bn = blockIdx.x * BN;
    const int bm = blockIdx.y * BM;

    sbias[tid] = bias[bn + tid];

    // global->smem: 64 B per row -> 4 threads/row (chunk = 16 B)
    const int lrow = tid >> 2;         // 0..63
    const int lchk = (tid & 3) * 8;    // halves

    const __half* gA[2];
    uint32_t sA[2];
    #pragma unroll
    for (int i = 0; i < 2; i++) {
        int row = lrow + 64 * i;
        int ar = bm + row; if (ar >= M) ar = M - 1;
        gA[i] = A + (size_t)ar * DIM_FC + lchk;
        sA[i] = sbase + (row * BK + lchk) * 2;
    }
    const __half* gB[4];
    uint32_t sB[4];
    #pragma unroll
    for (int i = 0; i < 4; i++) {
        int row = lrow + 64 * i;
        gB[i] = BT + (size_t)(bn + row) * DIM_FC + lchk;
        sB[i] = sbase + (ATILE + row * BK + lchk) * 2;
    }

    float acc[4][8][4];
    #pragma unroll
    for (int mf = 0; mf < 4; mf++)
        #pragma unroll
        for (int nf = 0; nf < 8; nf++)
            #pragma unroll
            for (int qq = 0; qq < 4; qq++) acc[mf][nf][qq] = 0.0f;

    // prologue: issue k-tiles 0,1 into stages 0,1 (prefetch distance 2)
    #pragma unroll
    for (int j = 0; j < 2; j++) {
        uint32_t soff = j * STAGE * 2;
        int goff = j * BK;
        #pragma unroll
        for (int i = 0; i < 2; i++) CP_ASYNC16(sA[i] + soff, gA[i] + goff);
        #pragma unroll
        for (int i = 0; i < 4; i++) CP_ASYNC16(sB[i] + soff, gB[i] + goff);
        CP_COMMIT();
    }

    const int g  = lane >> 2;          // 0..7
    const int c0 = lane & 3;           // 0..3

    for (int kt = 0; kt < NKT; kt++) {
        if (kt + 2 < NKT) {
            uint32_t soff = ((kt + 2) & (NSTG - 1)) * STAGE * 2;
            int goff = (kt + 2) * BK;
            #pragma unroll
            for (int i = 0; i < 2; i++) CP_ASYNC16(sA[i] + soff, gA[i] + goff);
            #pragma unroll
            for (int i = 0; i < 4; i++) CP_ASYNC16(sB[i] + soff, gB[i] + goff);
        }
        CP_COMMIT();
        CP_WAIT(2);
        __syncthreads();

        const __half* As = smem + (kt & (NSTG - 1)) * STAGE;
        const __half* Bs = As + ATILE;

        // fragments: one LDS.128 per row covers both k16 chunks (perm layout)
        uint4 av[4][2];
        #pragma unroll
        for (int mf = 0; mf < 4; mf++) {
            const __half* ap = As + (wm * 64 + mf * 16 + g) * BK + c0 * 8;
            av[mf][0] = *(const uint4*)ap;
            av[mf][1] = *(const uint4*)(ap + 8 * BK);
        }
        uint4 bv[8];
        #pragma unroll
        for (int nf = 0; nf < 8; nf++)
            bv[nf] = *(const uint4*)(Bs + (wn * 64 + nf * 8 + g) * BK + c0 * 8);

        #pragma unroll
        for (int mf = 0; mf < 4; mf++)
            #pragma unroll
            for (int nf = 0; nf < 8; nf++) {
                // chunk 0: pairs {c0, c0+4}
                mma_f16(acc[mf][nf], av[mf][0].x, av[mf][1].x, av[mf][0].y, av[mf][1].y,
                        bv[nf].x, bv[nf].y);
                // chunk 1: pairs {c0+8, c0+12}
                mma_f16(acc[mf][nf], av[mf][0].z, av[mf][1].z, av[mf][0].w, av[mf][1].w,
                        bv[nf].z, bv[nf].w);
            }
    }

    // epilogue: bias + relu + store
    #pragma unroll
    for (int mf = 0; mf < 4; mf++) {
        int row0 = bm + wm * 64 + mf * 16 + g;
        #pragma unroll
        for (int nf = 0; nf < 8; nf++) {
            int coll = wn * 64 + nf * 8 + c0 * 2;
            float bx = sbias[coll], by = sbias[coll + 1];
            #pragma unroll
            for (int half_ = 0; half_ < 2; half_++) {
                int row = row0 + half_ * 8;
                if (row < M) {
                    float vx = fmaxf(acc[mf][nf][half_ * 2 + 0] + bx, 0.0f);
                    float vy = fmaxf(acc[mf][nf][half_ * 2 + 1] + by, 0.0f);
                    if (PERM_OUT) {
                        int cx = bn + coll;
                        int p = (cx & 31) >> 1;
                        int pp = ((p & 3) << 2) | (p >> 2);
                        __half2* dst = (__half2*)((__half*)Cout +
                                       (size_t)row * DIM_FC + (cx & ~31) + 2 * pp);
                        *dst = __floats2half2_rn(vx, vy);
                    } else {
                        float2 v; v.x = vx; v.y = vy;
                        *(float2*)((float*)Cout + (size_t)row * DIM_FC + bn + coll) = v;
                    }
                }
            }
        }
    }
}

// ---------------- kernel 5: final 1024 -> 3 projection ---------------------
__global__ void gemm3_kernel(const float* __restrict__ W3, const float* __restrict__ b3,
                             float* __restrict__ out) {
    __shared__ float sW[DIM_FC * NLAB];
    int tid = threadIdx.x;
    for (int i = tid; i < DIM_FC * NLAB; i += 256) sW[i] = W3[i];
    __syncthreads();

    int warp = tid >> 5;
    int lane = tid & 31;
    int r = blockIdx.x * 8 + warp;
    if (r >= NLINES) return;

    float a0 = 0.f, a1 = 0.f, a2 = 0.f;
    const float* hrow = g_h2 + (size_t)r * DIM_FC;
    for (int k = lane; k < DIM_FC; k += 32) {
        float h = hrow[k];
        a0 = fmaf(h, sW[k * 3 + 0], a0);
        a1 = fmaf(h, sW[k * 3 + 1], a1);
        a2 = fmaf(h, sW[k * 3 + 2], a2);
    }
    #pragma unroll
    for (int off = 16; off > 0; off >>= 1) {
        a0 += __shfl_down_sync(0xFFFFFFFFu, a0, off);
        a1 += __shfl_down_sync(0xFFFFFFFFu, a1, off);
        a2 += __shfl_down_sync(0xFFFFFFFFu, a2, off);
    }
    if (lane == 0) {
        out[r * 3 + 0] = a0 + b3[0];
        out[r * 3 + 1] = a1 + b3[1];
        out[r * 3 + 2] = a2 + b3[2];
    }
}

// ---------------- launch ---------------------------------------------------
extern "C" void kernel_launch(void* const* d_in, const int* in_sizes, int n_in,
                              void* d_out, int out_size) {
    const float* jloc = (const float*)d_in[0];
    const float* joff = (const float*)d_in[1];
    const float* loi  = (const float*)d_in[2];
    const int*   edge = (const int*)d_in[3];
    const float* W1   = (const float*)d_in[4];
    const float* b1   = (const float*)d_in[5];
    const float* W2   = (const float*)d_in[6];
    const float* b2   = (const float*)d_in[7];
    const float* W3   = (const float*)d_in[8];
    const float* b3   = (const float*)d_in[9];
    float* out = (float*)d_out;

    const int GEMM_SMEM = NSTG * STAGE * sizeof(__half);   // 98304 B
    cudaFuncSetAttribute(hgemm_kernel<true>,
                         cudaFuncAttributeMaxDynamicSharedMemorySize, GEMM_SMEM);
    cudaFuncSetAttribute(hgemm_kernel<false>,
                         cudaFuncAttributeMaxDynamicSharedMemorySize, GEMM_SMEM);

    __half *feats, *h1, *w1T, *w2T;
    float *h2;
    cudaGetSymbolAddress((void**)&feats, g_feats);
    cudaGetSymbolAddress((void**)&h1, g_h1);
    cudaGetSymbolAddress((void**)&h2, g_h2);
    cudaGetSymbolAddress((void**)&w1T, g_w1T);
    cudaGetSymbolAddress((void**)&w2T, g_w2T);

    topk_juncs_kernel<<<1, 1024>>>(jloc, joff);
    transpose_loi_kernel<<<dim3(NPIX / 32, DIM_LOI / 32), dim3(32, 8)>>>(loi);
    transposeW_kernel<<<dim3(32, 32), dim3(32, 8)>>>(W1, w1T);
    transposeW_kernel<<<dim3(32, 32), dim3(32, 8)>>>(W2, w2T);
    sample_kernel<<<NLINES, 128>>>(edge);

    dim3 ggrid(DIM_FC / BN, (NLINES + BM - 1) / BM);
    hgemm_kernel<true ><<<ggrid, 256, GEMM_SMEM>>>(feats, w1T, b1, h1, NLINES);
    hgemm_kernel<false><<<ggrid, 256, GEMM_SMEM>>>(h1, w2T, b2, h2, NLINES);

    gemm3_kernel<<<(NLINES + 7) / 8, 256>>>(W3, b3, out);
}

// round 9
// speedup vs baseline: 4.8469x; 1.0395x over previous
#include <cuda_runtime.h>
#include <cuda_fp16.h>
#include <math.h>
#include <cstdint>

#define HW 128
#define NPIX (HW*HW)          // 16384
#define TOPK 300
#define NLINES 20000
#define DIM_LOI 128
#define NPTS0 32
#define NPTS1 8
#define DIM_FC 1024
#define NLAB 3

// pair-permutation within a 32-k block (16 pairs): p' = (p&3)*4 + (p>>2)
__host__ __device__ __forceinline__ int khperm(int k) {
    int p = k >> 1;
    int pp = ((p & 3) << 2) | (p >> 2);
    return (pp << 1) | (k & 1);
}

// ---------------- scratch (device globals; no allocation allowed) ----------
__device__ __align__(16) __half g_loiTh[NPIX * DIM_LOI];   // [hw][c] fp16 4 MB
__device__ __align__(16) float  g_juncs[TOPK * 2];
__device__ __align__(16) __half g_feats[NLINES * DIM_FC];  // permuted fp16
__device__ __align__(16) __half g_h1[NLINES * DIM_FC];     // permuted fp16
__device__ __align__(16) __half g_w1T[DIM_FC * DIM_FC];    // W1^T [N][kperm]
__device__ __align__(16) __half g_w2T[DIM_FC * DIM_FC];    // W2^T [N][kperm]
__device__ __align__(16) float  g_part[4 * NLINES * NLAB]; // fused-out partials

// ======================= PTX helpers ========================================
__device__ __forceinline__ uint32_t smem_u32(const void* p) {
    uint32_t a;
    asm("{ .reg .u64 t; cvta.to.shared.u64 t, %1; cvt.u32.u64 %0, t; }" : "=r"(a) : "l"(p));
    return a;
}
#define CP_ASYNC16(sm, g) \
    asm volatile("cp.async.cg.shared.global [%0], [%1], 16;" :: "r"(sm), "l"(g) : "memory")
#define CP_COMMIT() asm volatile("cp.async.commit_group;" ::: "memory")
#define CP_WAIT(n)  asm volatile("cp.async.wait_group %0;" :: "n"(n) : "memory")

__device__ __forceinline__ void mma_f16(float* c,
                                        uint32_t a0, uint32_t a1, uint32_t a2, uint32_t a3,
                                        uint32_t b0, uint32_t b1) {
    asm volatile(
        "mma.sync.aligned.m16n8k16.row.col.f32.f16.f16.f32 "
        "{%0,%1,%2,%3}, {%4,%5,%6,%7}, {%8,%9}, {%0,%1,%2,%3};"
        : "+f"(c[0]), "+f"(c[1]), "+f"(c[2]), "+f"(c[3])
        : "r"(a0), "r"(a1), "r"(a2), "r"(a3), "r"(b0), "r"(b1));
}

// ---------------- kernel 1: NMS + compact + small bitonic top-k ------------
#define SORTN 4096
__global__ void topk_juncs_kernel(const float* __restrict__ jloc,
                                  const float* __restrict__ joff) {
    __shared__ unsigned long long keys[SORTN];
    __shared__ int cnt;
    int tid = threadIdx.x;
    if (tid == 0) cnt = 0;
    #pragma unroll
    for (int i = tid; i < SORTN; i += 1024) keys[i] = 0ull;
    __syncthreads();

    for (int i = tid; i < NPIX; i += 1024) {
        int y = i >> 7, x = i & 127;
        float v = jloc[i];
        float m = v;
        #pragma unroll
        for (int dy = -1; dy <= 1; dy++)
            #pragma unroll
            for (int dx = -1; dx <= 1; dx++) {
                int yy = y + dy, xx = x + dx;
                if (yy >= 0 && yy < HW && xx >= 0 && xx < HW)
                    m = fmaxf(m, jloc[yy * HW + xx]);
            }
        if (v == m && v > 0.0f) {
            int p = atomicAdd(&cnt, 1);
            if (p < SORTN)
                keys[p] = ((unsigned long long)__float_as_uint(v) << 32)
                        | (unsigned long long)(0xFFFFFFFFu - (unsigned)i);
        }
    }
    __syncthreads();

    for (int k = 2; k <= SORTN; k <<= 1) {
        for (int j = k >> 1; j > 0; j >>= 1) {
            #pragma unroll
            for (int i = tid; i < SORTN; i += 1024) {
                int ixj = i ^ j;
                if (ixj > i) {
                    unsigned long long a = keys[i], b = keys[ixj];
                    bool up = ((i & k) == 0);
                    if ((a < b) == up) { keys[i] = b; keys[ixj] = a; }
                }
            }
            __syncthreads();
        }
    }

    if (tid < TOPK) {
        unsigned long long key = keys[tid];
        unsigned idx = 0xFFFFFFFFu - (unsigned)(key & 0xFFFFFFFFull);
        float j0 = joff[idx];
        float j1 = joff[NPIX + idx];
        float sx = 1.0f / (1.0f + expf(-j0));
        float sy = 1.0f / (1.0f + expf(-j1));
        g_juncs[2 * tid + 0] = (float)(idx & 127) + sx;
        g_juncs[2 * tid + 1] = (float)(idx >> 7) + sy;
    }
}

// ---------------- kernel 2a: transpose loi [C][HW*HW] -> [HW*HW][C] fp16 ---
__global__ void transpose_loi_kernel(const float* __restrict__ in) {
    __shared__ float tile[32][33];
    int p0 = blockIdx.x * 32;
    int c0 = blockIdx.y * 32;
    int tx = threadIdx.x, ty = threadIdx.y;   // 32 x 8
    #pragma unroll
    for (int i = 0; i < 32; i += 8)
        tile[ty + i][tx] = in[(size_t)(c0 + ty + i) * NPIX + p0 + tx];
    __syncthreads();
    #pragma unroll
    for (int i = 0; i < 32; i += 8)
        g_loiTh[(size_t)(p0 + ty + i) * DIM_LOI + c0 + tx] =
            __float2half_rn(tile[tx][ty + i]);
}

// ---------------- kernel 2b: W -> W^T with k-perm + fp16 -------------------
__global__ void transposeW_kernel(const float* __restrict__ in, __half* __restrict__ out) {
    __shared__ float tile[32][33];
    int p0 = blockIdx.x * 32;   // n block
    int c0 = blockIdx.y * 32;   // k block
    int tx = threadIdx.x, ty = threadIdx.y;   // 32 x 8
    #pragma unroll
    for (int i = 0; i < 32; i += 8)
        tile[ty + i][tx] = in[(size_t)(c0 + ty + i) * DIM_FC + p0 + tx];
    __syncthreads();
    #pragma unroll
    for (int i = 0; i < 32; i += 8)
        out[(size_t)(p0 + ty + i) * DIM_FC + c0 + khperm(tx)] =
            __float2half_rn(tile[tx][ty + i]);
}

// ---------------- kernel 3: line sampling + bilinear + group max -----------
// 128 threads: quad q=tid>>5 handles 2 maxpool groups, lane handles 4 channels.
__global__ void sample_kernel(const int* __restrict__ edge) {
    __shared__ int   s_off[NPTS0][4];
    __shared__ float s_w[NPTS0][4];
    __shared__ float s_out[DIM_FC];

    int n = blockIdx.x;
    int tid = threadIdx.x;
    int lane = tid & 31;
    int q = tid >> 5;

    if (tid < NPTS0) {
        int e0 = edge[2 * n + 0];
        int e1 = edge[2 * n + 1];
        float Ux = g_juncs[2 * e0 + 0], Uy = g_juncs[2 * e0 + 1];
        float Vx = g_juncs[2 * e1 + 0], Vy = g_juncs[2 * e1 + 1];
        float t = (float)tid * (1.0f / 31.0f);
        float px = Ux * t + Vx * (1.0f - t) - 0.5f;
        float py = Uy * t + Vy * (1.0f - t) - 0.5f;
        float x0 = fminf(fmaxf(floorf(px), 0.0f), 127.0f);
        float y0 = fminf(fmaxf(floorf(py), 0.0f), 127.0f);
        float x1 = fminf(x0 + 1.0f, 127.0f);
        float y1 = fminf(y0 + 1.0f, 127.0f);
        int ix0 = (int)x0, iy0 = (int)y0, ix1 = (int)x1, iy1 = (int)y1;
        s_off[tid][0] = (iy0 * HW + ix0) * DIM_LOI;
        s_off[tid][1] = (iy1 * HW + ix0) * DIM_LOI;
        s_off[tid][2] = (iy0 * HW + ix1) * DIM_LOI;
        s_off[tid][3] = (iy1 * HW + ix1) * DIM_LOI;
        s_w[tid][0] = (y1 - py) * (x1 - px);
        s_w[tid][1] = (py - y0) * (x1 - px);
        s_w[tid][2] = (y1 - py) * (px - x0);
        s_w[tid][3] = (py - y0) * (px - x0);
    }
    __syncthreads();

    int cq = lane;   // channels 4*lane .. 4*lane+3 (8 bytes fp16)

    #pragma unroll
    for (int j2 = 0; j2 < 2; j2++) {
        int j = q * 2 + j2;
        float4 m = make_float4(-1e30f, -1e30f, -1e30f, -1e30f);
        #pragma unroll
        for (int k = 0; k < 4; k++) {
            int p = j * 4 + k;
            float w0 = s_w[p][0], w1 = s_w[p][1], w2 = s_w[p][2], w3 = s_w[p][3];
            const __half2* r0 = (const __half2*)(g_loiTh + s_off[p][0] + cq * 4);
            const __half2* r1 = (const __half2*)(g_loiTh + s_off[p][1] + cq * 4);
            const __half2* r2 = (const __half2*)(g_loiTh + s_off[p][2] + cq * 4);
            const __half2* r3 = (const __half2*)(g_loiTh + s_off[p][3] + cq * 4);
            float2 a0 = __half22float2(r0[0]), a1 = __half22float2(r0[1]);
            float2 b0 = __half22float2(r1[0]), b1 = __half22float2(r1[1]);
            float2 c0 = __half22float2(r2[0]), c1 = __half22float2(r2[1]);
            float2 d0 = __half22float2(r3[0]), d1 = __half22float2(r3[1]);
            float4 v;
            v.x = w0 * a0.x + w1 * b0.x + w2 * c0.x + w3 * d0.x;
            v.y = w0 * a0.y + w1 * b0.y + w2 * c0.y + w3 * d0.y;
            v.z = w0 * a1.x + w1 * b1.x + w2 * c1.x + w3 * d1.x;
            v.w = w0 * a1.y + w1 * b1.y + w2 * c1.y + w3 * d1.y;
            m.x = fmaxf(m.x, v.x); m.y = fmaxf(m.y, v.y);
            m.z = fmaxf(m.z, v.z); m.w = fmaxf(m.w, v.w);
        }
        s_out[(cq * 4 + 0) * NPTS1 + j] = m.x;
        s_out[(cq * 4 + 1) * NPTS1 + j] = m.y;
        s_out[(cq * 4 + 2) * NPTS1 + j] = m.z;
        s_out[(cq * 4 + 3) * NPTS1 + j] = m.w;
    }
    __syncthreads();

    for (int f = tid; f < DIM_FC; f += 128) {
        int pos = (f & ~31) | khperm(f & 31);
        g_feats[(size_t)n * DIM_FC + pos] = __float2half_rn(s_out[f]);
    }
}

// ---------------- kernel 4: fp16 mma GEMM, 128x256 tile, 64x64 warp tile ---
// MODE 0: C = relu(A@BT^T + bias), fp16 k-permuted out (feeds next GEMM)
// MODE 1: fused final: partial[bx][row][lab] = sum_cols relu(acc+bias)*W3[col][lab]
#define BK 32                          // halves per k-tile (64 B per row)
#define NKT (DIM_FC / BK)              // 32
#define BM 128
#define BN 256
#define ATILE (BM * BK)
#define BTILE (BN * BK)
#define STAGE (ATILE + BTILE)          // 12288 halves = 24 KB
#define NSTG 4

template <int MODE>
__global__ __launch_bounds__(256, 1)
void hgemm_kernel(const __half* __restrict__ A, const __half* __restrict__ BT,
                  const float* __restrict__ bias, const float* __restrict__ W3,
                  void* __restrict__ Cout, int M)
{
    extern __shared__ __half smem[];   // [NSTG][A | B]
    __shared__ float sbias[BN];
    __shared__ float sW3[BN * NLAB];
    __shared__ float sP[4][BM][NLAB];
    const uint32_t sbase = smem_u32(smem);
    const int tid = threadIdx.x;
    const int lane = tid & 31;
    const int warp = tid >> 5;
    const int wm = warp & 1;
    const int wn = warp >> 1;
    const int bn = blockIdx.x * BN;
    const int bm = blockIdx.y * BM;

    sbias[tid] = bias[bn + tid];
    if (MODE == 1) {
        #pragma unroll
        for (int i = tid; i < BN * NLAB; i += 256) sW3[i] = W3[bn * NLAB + i];
    }

    const int lrow = tid >> 2;
    const int lchk = (tid & 3) * 8;

    const __half* gA[2];
    uint32_t sA[2];
    #pragma unroll
    for (int i = 0; i < 2; i++) {
        int row = lrow + 64 * i;
        int ar = bm + row; if (ar >= M) ar = M - 1;
        gA[i] = A + (size_t)ar * DIM_FC + lchk;
        sA[i] = sbase + (row * BK + lchk) * 2;
    }
    const __half* gB[4];
    uint32_t sB[4];
    #pragma unroll
    for (int i = 0; i < 4; i++) {
        int row = lrow + 64 * i;
        gB[i] = BT + (size_t)(bn + row) * DIM_FC + lchk;
        sB[i] = sbase + (ATILE + row * BK + lchk) * 2;
    }

    float acc[4][8][4];
    #pragma unroll
    for (int mf = 0; mf < 4; mf++)
        #pragma unroll
        for (int nf = 0; nf < 8; nf++)
            #pragma unroll
            for (int qq = 0; qq < 4; qq++) acc[mf][nf][qq] = 0.0f;

    #pragma unroll
    for (int j = 0; j < 2; j++) {
        uint32_t soff = j * STAGE * 2;
        int goff = j * BK;
        #pragma unroll
        for (int i = 0; i < 2; i++) CP_ASYNC16(sA[i] + soff, gA[i] + goff);
        #pragma unroll
        for (int i = 0; i < 4; i++) CP_ASYNC16(sB[i] + soff, gB[i] + goff);
        CP_COMMIT();
    }

    const int g  = lane >> 2;
    const int c0 = lane & 3;

    for (int kt = 0; kt < NKT; kt++) {
        if (kt + 2 < NKT) {
            uint32_t soff = ((kt + 2) & (NSTG - 1)) * STAGE * 2;
            int goff = (kt + 2) * BK;
            #pragma unroll
            for (int i = 0; i < 2; i++) CP_ASYNC16(sA[i] + soff, gA[i] + goff);
            #pragma unroll
            for (int i = 0; i < 4; i++) CP_ASYNC16(sB[i] + soff, gB[i] + goff);
        }
        CP_COMMIT();
        CP_WAIT(2);
        __syncthreads();

        const __half* As = smem + (kt & (NSTG - 1)) * STAGE;
        const __half* Bs = As + ATILE;

        uint4 av[4][2];
        #pragma unroll
        for (int mf = 0; mf < 4; mf++) {
            const __half* ap = As + (wm * 64 + mf * 16 + g) * BK + c0 * 8;
            av[mf][0] = *(const uint4*)ap;
            av[mf][1] = *(const uint4*)(ap + 8 * BK);
        }
        uint4 bv[8];
        #pragma unroll
        for (int nf = 0; nf < 8; nf++)
            bv[nf] = *(const uint4*)(Bs + (wn * 64 + nf * 8 + g) * BK + c0 * 8);

        #pragma unroll
        for (int mf = 0; mf < 4; mf++)
            #pragma unroll
            for (int nf = 0; nf < 8; nf++) {
                mma_f16(acc[mf][nf], av[mf][0].x, av[mf][1].x, av[mf][0].y, av[mf][1].y,
                        bv[nf].x, bv[nf].y);
                mma_f16(acc[mf][nf], av[mf][0].z, av[mf][1].z, av[mf][0].w, av[mf][1].w,
                        bv[nf].z, bv[nf].w);
            }
    }

    if (MODE == 0) {
        // epilogue: bias + relu + fp16-permuted store
        #pragma unroll
        for (int mf = 0; mf < 4; mf++) {
            int row0 = bm + wm * 64 + mf * 16 + g;
            #pragma unroll
            for (int nf = 0; nf < 8; nf++) {
                int coll = wn * 64 + nf * 8 + c0 * 2;
                float bx = sbias[coll], by = sbias[coll + 1];
                #pragma unroll
                for (int half_ = 0; half_ < 2; half_++) {
                    int row = row0 + half_ * 8;
                    if (row < M) {
                        float vx = fmaxf(acc[mf][nf][half_ * 2 + 0] + bx, 0.0f);
                        float vy = fmaxf(acc[mf][nf][half_ * 2 + 1] + by, 0.0f);
                        int cx = bn + coll;
                        int p = (cx & 31) >> 1;
                        int pp = ((p & 3) << 2) | (p >> 2);
                        __half2* dst = (__half2*)((__half*)Cout +
                                       (size_t)row * DIM_FC + (cx & ~31) + 2 * pp);
                        *dst = __floats2half2_rn(vx, vy);
                    }
                }
            }
        }
    } else {
        // fused epilogue: relu(acc+bias) . W3 over this block's 256 cols
        #pragma unroll
        for (int mf = 0; mf < 4; mf++) {
            #pragma unroll
            for (int half_ = 0; half_ < 2; half_++) {
                float p0 = 0.f, p1 = 0.f, p2 = 0.f;
                #pragma unroll
                for (int nf = 0; nf < 8; nf++) {
                    int coll = wn * 64 + nf * 8 + c0 * 2;
                    float vx = fmaxf(acc[mf][nf][half_ * 2 + 0] + sbias[coll], 0.0f);
                    float vy = fmaxf(acc[mf][nf][half_ * 2 + 1] + sbias[coll + 1], 0.0f);
                    p0 += vx * sW3[coll * 3 + 0] + vy * sW3[coll * 3 + 3];
                    p1 += vx * sW3[coll * 3 + 1] + vy * sW3[coll * 3 + 4];
                    p2 += vx * sW3[coll * 3 + 2] + vy * sW3[coll * 3 + 5];
                }
                // reduce over the c0 quad (lanes 4g..4g+3 share this row)
                p0 += __shfl_xor_sync(0xFFFFFFFFu, p0, 1);
                p1 += __shfl_xor_sync(0xFFFFFFFFu, p1, 1);
                p2 += __shfl_xor_sync(0xFFFFFFFFu, p2, 1);
                p0 += __shfl_xor_sync(0xFFFFFFFFu, p0, 2);
                p1 += __shfl_xor_sync(0xFFFFFFFFu, p1, 2);
                p2 += __shfl_xor_sync(0xFFFFFFFFu, p2, 2);
                if (c0 == 0) {
                    int lr = wm * 64 + mf * 16 + g + half_ * 8;
                    sP[wn][lr][0] = p0;
                    sP[wn][lr][1] = p1;
                    sP[wn][lr][2] = p2;
                }
            }
        }
        __syncthreads();
        float* part = (float*)Cout + (size_t)blockIdx.x * NLINES * NLAB;
        for (int i = tid; i < BM * NLAB; i += 256) {
            int lr = i / NLAB, lab = i % NLAB;
            int row = bm + lr;
            if (row < M)
                part[(size_t)row * NLAB + lab] =
                    sP[0][lr][lab] + sP[1][lr][lab] + sP[2][lr][lab] + sP[3][lr][lab];
        }
    }
}

// ---------------- kernel 5: reduce 4 partials + bias -> out ----------------
__global__ void reduce_out_kernel(const float* __restrict__ b3, float* __restrict__ out) {
    int i = blockIdx.x * 256 + threadIdx.x;
    if (i < NLINES * NLAB) {
        int lab = i % NLAB;
        out[i] = b3[lab] + g_part[i] + g_part[NLINES * NLAB + i]
               + g_part[2 * NLINES * NLAB + i] + g_part[3 * NLINES * NLAB + i];
    }
}

// ---------------- launch ---------------------------------------------------
extern "C" void kernel_launch(void* const* d_in, const int* in_sizes, int n_in,
                              void* d_out, int out_size) {
    const float* jloc = (const float*)d_in[0];
    const float* joff = (const float*)d_in[1];
    const float* loi  = (const float*)d_in[2];
    const int*   edge = (const int*)d_in[3];
    const float* W1   = (const float*)d_in[4];
    const float* b1   = (const float*)d_in[5];
    const float* W2   = (const float*)d_in[6];
    const float* b2   = (const float*)d_in[7];
    const float* W3   = (const float*)d_in[8];
    const float* b3   = (const float*)d_in[9];
    float* out = (float*)d_out;

    const int GEMM_SMEM = NSTG * STAGE * sizeof(__half);   // 98304 B
    cudaFuncSetAttribute(hgemm_kernel<0>,
                         cudaFuncAttributeMaxDynamicSharedMemorySize, GEMM_SMEM);
    cudaFuncSetAttribute(hgemm_kernel<1>,
                         cudaFuncAttributeMaxDynamicSharedMemorySize, GEMM_SMEM);

    __half *feats, *h1, *w1T, *w2T;
    float *part;
    cudaGetSymbolAddress((void**)&feats, g_feats);
    cudaGetSymbolAddress((void**)&h1, g_h1);
    cudaGetSymbolAddress((void**)&w1T, g_w1T);
    cudaGetSymbolAddress((void**)&w2T, g_w2T);
    cudaGetSymbolAddress((void**)&part, g_part);

    topk_juncs_kernel<<<1, 1024>>>(jloc, joff);
    transpose_loi_kernel<<<dim3(NPIX / 32, DIM_LOI / 32), dim3(32, 8)>>>(loi);
    transposeW_kernel<<<dim3(32, 32), dim3(32, 8)>>>(W1, w1T);
    transposeW_kernel<<<dim3(32, 32), dim3(32, 8)>>>(W2, w2T);
    sample_kernel<<<NLINES, 128>>>(edge);

    dim3 ggrid(DIM_FC / BN, (NLINES + BM - 1) / BM);
    hgemm_kernel<0><<<ggrid, 256, GEMM_SMEM>>>(feats, w1T, b1, nullptr, h1, NLINES);
    hgemm_kernel<1><<<ggrid, 256, GEMM_SMEM>>>(h1, w2T, b2, W3, part, NLINES);

    reduce_out_kernel<<<(NLINES * NLAB + 255) / 256, 256>>>(b3, out);
}

// round 11
// speedup vs baseline: 6.0376x; 1.2456x over previous
#include <cuda_runtime.h>
#include <cuda_fp16.h>
#include <math.h>
#include <cstdint>

#define HW 128
#define NPIX (HW*HW)          // 16384
#define TOPK 300
#define NLINES 20000
#define DIM_LOI 128
#define NPTS0 32
#define NPTS1 8
#define DIM_FC 1024
#define NLAB 3

// pair-permutation within a 32-k block (16 pairs): p' = (p&3)*4 + (p>>2)
__host__ __device__ __forceinline__ int khperm(int k) {
    int p = k >> 1;
    int pp = ((p & 3) << 2) | (p >> 2);
    return (pp << 1) | (k & 1);
}

// ---------------- scratch (device globals; no allocation allowed) ----------
__device__ __align__(16) __half g_loiTh[NPIX * DIM_LOI];   // [hw][c] fp16 4 MB
__device__ __align__(16) float  g_juncs[TOPK * 2];
__device__ __align__(16) __half g_feats[NLINES * DIM_FC];  // permuted fp16
__device__ __align__(16) __half g_h1[NLINES * DIM_FC];     // permuted fp16
__device__ __align__(16) __half g_w1T[DIM_FC * DIM_FC];    // W1^T [N][kperm]
__device__ __align__(16) __half g_w2T[DIM_FC * DIM_FC];    // W2^T [N][kperm]
__device__ __align__(16) float  g_part[8 * NLINES * NLAB]; // fused-out partials

// ======================= PTX helpers ========================================
__device__ __forceinline__ uint32_t smem_u32(const void* p) {
    uint32_t a;
    asm("{ .reg .u64 t; cvta.to.shared.u64 t, %1; cvt.u32.u64 %0, t; }" : "=r"(a) : "l"(p));
    return a;
}
#define CP_ASYNC16(sm, g) \
    asm volatile("cp.async.cg.shared.global [%0], [%1], 16;" :: "r"(sm), "l"(g) : "memory")
#define CP_COMMIT() asm volatile("cp.async.commit_group;" ::: "memory")
#define CP_WAIT(n)  asm volatile("cp.async.wait_group %0;" :: "n"(n) : "memory")

__device__ __forceinline__ void mma_f16(float* c,
                                        uint32_t a0, uint32_t a1, uint32_t a2, uint32_t a3,
                                        uint32_t b0, uint32_t b1) {
    asm volatile(
        "mma.sync.aligned.m16n8k16.row.col.f32.f16.f16.f32 "
        "{%0,%1,%2,%3}, {%4,%5,%6,%7}, {%8,%9}, {%0,%1,%2,%3};"
        : "+f"(c[0]), "+f"(c[1]), "+f"(c[2]), "+f"(c[3])
        : "r"(a0), "r"(a1), "r"(a2), "r"(a3), "r"(b0), "r"(b1));
}

// ---------------- kernel 1: NMS + compact + small bitonic top-k ------------
#define SORTN 4096
__global__ void topk_juncs_kernel(const float* __restrict__ jloc,
                                  const float* __restrict__ joff) {
    __shared__ unsigned long long keys[SORTN];
    __shared__ int cnt;
    int tid = threadIdx.x;
    if (tid == 0) cnt = 0;
    #pragma unroll
    for (int i = tid; i < SORTN; i += 1024) keys[i] = 0ull;
    __syncthreads();

    for (int i = tid; i < NPIX; i += 1024) {
        int y = i >> 7, x = i & 127;
        float v = jloc[i];
        float m = v;
        #pragma unroll
        for (int dy = -1; dy <= 1; dy++)
            #pragma unroll
            for (int dx = -1; dx <= 1; dx++) {
                int yy = y + dy, xx = x + dx;
                if (yy >= 0 && yy < HW && xx >= 0 && xx < HW)
                    m = fmaxf(m, jloc[yy * HW + xx]);
            }
        if (v == m && v > 0.0f) {
            int p = atomicAdd(&cnt, 1);
            if (p < SORTN)
                keys[p] = ((unsigned long long)__float_as_uint(v) << 32)
                        | (unsigned long long)(0xFFFFFFFFu - (unsigned)i);
        }
    }
    __syncthreads();

    for (int k = 2; k <= SORTN; k <<= 1) {
        for (int j = k >> 1; j > 0; j >>= 1) {
            #pragma unroll
            for (int i = tid; i < SORTN; i += 1024) {
                int ixj = i ^ j;
                if (ixj > i) {
                    unsigned long long a = keys[i], b = keys[ixj];
                    bool up = ((i & k) == 0);
                    if ((a < b) == up) { keys[i] = b; keys[ixj] = a; }
                }
            }
            __syncthreads();
        }
    }

    if (tid < TOPK) {
        unsigned long long key = keys[tid];
        unsigned idx = 0xFFFFFFFFu - (unsigned)(key & 0xFFFFFFFFull);
        float j0 = joff[idx];
        float j1 = joff[NPIX + idx];
        float sx = 1.0f / (1.0f + expf(-j0));
        float sy = 1.0f / (1.0f + expf(-j1));
        g_juncs[2 * tid + 0] = (float)(idx & 127) + sx;
        g_juncs[2 * tid + 1] = (float)(idx >> 7) + sy;
    }
}

// ---------------- kernel 2a: transpose loi [C][HW*HW] -> [HW*HW][C] fp16 ---
__global__ void transpose_loi_kernel(const float* __restrict__ in) {
    __shared__ float tile[32][33];
    int p0 = blockIdx.x * 32;
    int c0 = blockIdx.y * 32;
    int tx = threadIdx.x, ty = threadIdx.y;   // 32 x 8
    #pragma unroll
    for (int i = 0; i < 32; i += 8)
        tile[ty + i][tx] = in[(size_t)(c0 + ty + i) * NPIX + p0 + tx];
    __syncthreads();
    #pragma unroll
    for (int i = 0; i < 32; i += 8)
        g_loiTh[(size_t)(p0 + ty + i) * DIM_LOI + c0 + tx] =
            __float2half_rn(tile[tx][ty + i]);
}

// ---------------- kernel 2b: both W -> W^T with k-perm + fp16 (z = which) --
__global__ void transposeW_kernel(const float* __restrict__ W1,
                                  const float* __restrict__ W2) {
    __shared__ float tile[32][33];
    const float* in = blockIdx.z ? W2 : W1;
    __half* out = blockIdx.z ? g_w2T : g_w1T;
    int p0 = blockIdx.x * 32;   // n block
    int c0 = blockIdx.y * 32;   // k block
    int tx = threadIdx.x, ty = threadIdx.y;   // 32 x 8
    #pragma unroll
    for (int i = 0; i < 32; i += 8)
        tile[ty + i][tx] = in[(size_t)(c0 + ty + i) * DIM_FC + p0 + tx];
    __syncthreads();
    #pragma unroll
    for (int i = 0; i < 32; i += 8)
        out[(size_t)(p0 + ty + i) * DIM_FC + c0 + khperm(tx)] =
            __float2half_rn(tile[tx][ty + i]);
}

// ---------------- kernel 3: line sampling + bilinear + group max -----------
// 128 threads: pg = tid>>4 (maxpool group 0..7), cq = tid&15 (8-ch chunk, 16 B)
__global__ void sample_kernel(const int* __restrict__ edge) {
    __shared__ int   s_off[NPTS0][4];
    __shared__ float s_w[NPTS0][4];
    __shared__ float s_out[DIM_FC];

    int n = blockIdx.x;
    int tid = threadIdx.x;
    int pg = tid >> 4;
    int cq = tid & 15;

    if (tid < NPTS0) {
        int e0 = edge[2 * n + 0];
        int e1 = edge[2 * n + 1];
        float Ux = g_juncs[2 * e0 + 0], Uy = g_juncs[2 * e0 + 1];
        float Vx = g_juncs[2 * e1 + 0], Vy = g_juncs[2 * e1 + 1];
        float t = (float)tid * (1.0f / 31.0f);
        float px = Ux * t + Vx * (1.0f - t) - 0.5f;
        float py = Uy * t + Vy * (1.0f - t) - 0.5f;
        float x0 = fminf(fmaxf(floorf(px), 0.0f), 127.0f);
        float y0 = fminf(fmaxf(floorf(py), 0.0f), 127.0f);
        float x1 = fminf(x0 + 1.0f, 127.0f);
        float y1 = fminf(y0 + 1.0f, 127.0f);
        int ix0 = (int)x0, iy0 = (int)y0, ix1 = (int)x1, iy1 = (int)y1;
        s_off[tid][0] = (iy0 * HW + ix0) * DIM_LOI;
        s_off[tid][1] = (iy1 * HW + ix0) * DIM_LOI;
        s_off[tid][2] = (iy0 * HW + ix1) * DIM_LOI;
        s_off[tid][3] = (iy1 * HW + ix1) * DIM_LOI;
        s_w[tid][0] = (y1 - py) * (x1 - px);
        s_w[tid][1] = (py - y0) * (x1 - px);
        s_w[tid][2] = (y1 - py) * (px - x0);
        s_w[tid][3] = (py - y0) * (px - x0);
    }
    __syncthreads();

    float m[8];
    #pragma unroll
    for (int i = 0; i < 8; i++) m[i] = -1e30f;

    #pragma unroll
    for (int k = 0; k < 4; k++) {
        int p = pg * 4 + k;
        float w0 = s_w[p][0], w1 = s_w[p][1], w2 = s_w[p][2], w3 = s_w[p][3];
        uint4 u0 = *(const uint4*)(g_loiTh + s_off[p][0] + cq * 8);
        uint4 u1 = *(const uint4*)(g_loiTh + s_off[p][1] + cq * 8);
        uint4 u2 = *(const uint4*)(g_loiTh + s_off[p][2] + cq * 8);
        uint4 u3 = *(const uint4*)(g_loiTh + s_off[p][3] + cq * 8);
        const __half2* h0 = (const __half2*)&u0;
        const __half2* h1 = (const __half2*)&u1;
        const __half2* h2 = (const __half2*)&u2;
        const __half2* h3 = (const __half2*)&u3;
        #pragma unroll
        for (int j = 0; j < 4; j++) {
            float2 a = __half22float2(h0[j]);
            float2 b = __half22float2(h1[j]);
            float2 c = __half22float2(h2[j]);
            float2 d = __half22float2(h3[j]);
            float vx = w0 * a.x + w1 * b.x + w2 * c.x + w3 * d.x;
            float vy = w0 * a.y + w1 * b.y + w2 * c.y + w3 * d.y;
            m[2 * j + 0] = fmaxf(m[2 * j + 0], vx);
            m[2 * j + 1] = fmaxf(m[2 * j + 1], vy);
        }
    }
    #pragma unroll
    for (int i = 0; i < 8; i++)
        s_out[(cq * 8 + i) * NPTS1 + pg] = m[i];
    __syncthreads();

    for (int f = tid; f < DIM_FC; f += 128) {
        int pos = (f & ~31) | khperm(f & 31);
        g_feats[(size_t)n * DIM_FC + pos] = __float2half_rn(s_out[f]);
    }
}

// ---------------- kernel 4: fp16 mma GEMM, 128x128 tile, 64x32 warp tile ---
// MODE 0: C = relu(A@BT^T + bias), fp16 k-permuted out
// MODE 1: fused final: partial[bx][row][lab] = sum_cols relu(acc+bias)*W3[col][lab]
#define BK 32                          // halves per k-tile (64 B per row)
#define NKT (DIM_FC / BK)              // 32
#define BM 128
#define BN 128
#define ATILE (BM * BK)                // 4096 halves
#define BTILE (BN * BK)
#define STAGE (ATILE + BTILE)          // 8192 halves = 16 KB
#define NSTG 4

template <int MODE>
__global__ __launch_bounds__(256, 2)
void hgemm_kernel(const __half* __restrict__ A, const __half* __restrict__ BT,
                  const float* __restrict__ bias, const float* __restrict__ W3,
                  void* __restrict__ Cout, int M)
{
    extern __shared__ __half smem[];   // [NSTG][A | B]
    __shared__ float sbias[BN];
    __shared__ float sW3[BN * NLAB];
    __shared__ float sP[4][BM][NLAB];
    const uint32_t sbase = smem_u32(smem);
    const int tid = threadIdx.x;
    const int lane = tid & 31;
    const int warp = tid >> 5;
    const int wm = warp & 1;           // 2 row slabs of 64
    const int wn = warp >> 1;          // 4 col slabs of 32
    const int bn = blockIdx.x * BN;
    const int bm = blockIdx.y * BM;

    if (tid < BN) sbias[tid] = bias[bn + tid];
    if (MODE == 1) {
        #pragma unroll
        for (int i = tid; i < BN * NLAB; i += 256) sW3[i] = W3[bn * NLAB + i];
    }

    const int lrow = tid >> 2;         // 0..63
    const int lchk = (tid & 3) * 8;    // halves (16 B chunk)

    const __half* gA[2];
    uint32_t sA[2];
    const __half* gB[2];
    uint32_t sB[2];
    #pragma unroll
    for (int i = 0; i < 2; i++) {
        int row = lrow + 64 * i;
        int ar = bm + row; if (ar >= M) ar = M - 1;
        gA[i] = A + (size_t)ar * DIM_FC + lchk;
        sA[i] = sbase + (row * BK + lchk) * 2;
        gB[i] = BT + (size_t)(bn + row) * DIM_FC + lchk;
        sB[i] = sbase + (ATILE + row * BK + lchk) * 2;
    }

    float acc[4][4][4];
    #pragma unroll
    for (int mf = 0; mf < 4; mf++)
        #pragma unroll
        for (int nf = 0; nf < 4; nf++)
            #pragma unroll
            for (int qq = 0; qq < 4; qq++) acc[mf][nf][qq] = 0.0f;

    #pragma unroll
    for (int j = 0; j < 2; j++) {
        uint32_t soff = j * STAGE * 2;
        int goff = j * BK;
        #pragma unroll
        for (int i = 0; i < 2; i++) {
            CP_ASYNC16(sA[i] + soff, gA[i] + goff);
            CP_ASYNC16(sB[i] + soff, gB[i] + goff);
        }
        CP_COMMIT();
    }

    const int g  = lane >> 2;
    const int c0 = lane & 3;

    for (int kt = 0; kt < NKT; kt++) {
        if (kt + 2 < NKT) {
            uint32_t soff = ((kt + 2) & (NSTG - 1)) * STAGE * 2;
            int goff = (kt + 2) * BK;
            #pragma unroll
            for (int i = 0; i < 2; i++) {
                CP_ASYNC16(sA[i] + soff, gA[i] + goff);
                CP_ASYNC16(sB[i] + soff, gB[i] + goff);
            }
        }
        CP_COMMIT();
        CP_WAIT(2);
        __syncthreads();

        const __half* As = smem + (kt & (NSTG - 1)) * STAGE;
        const __half* Bs = As + ATILE;

        uint4 av[4][2];
        #pragma unroll
        for (int mf = 0; mf < 4; mf++) {
            const __half* ap = As + (wm * 64 + mf * 16 + g) * BK + c0 * 8;
            av[mf][0] = *(const uint4*)ap;
            av[mf][1] = *(const uint4*)(ap + 8 * BK);
        }
        uint4 bv[4];
        #pragma unroll
        for (int nf = 0; nf < 4; nf++)
            bv[nf] = *(const uint4*)(Bs + (wn * 32 + nf * 8 + g) * BK + c0 * 8);

        #pragma unroll
        for (int mf = 0; mf < 4; mf++)
            #pragma unroll
            for (int nf = 0; nf < 4; nf++) {
                mma_f16(acc[mf][nf], av[mf][0].x, av[mf][1].x, av[mf][0].y, av[mf][1].y,
                        bv[nf].x, bv[nf].y);
                mma_f16(acc[mf][nf], av[mf][0].z, av[mf][1].z, av[mf][0].w, av[mf][1].w,
                        bv[nf].z, bv[nf].w);
            }
    }

    if (MODE == 0) {
        #pragma unroll
        for (int mf = 0; mf < 4; mf++) {
            int row0 = bm + wm * 64 + mf * 16 + g;
            #pragma unroll
            for (int nf = 0; nf < 4; nf++) {
                int coll = wn * 32 + nf * 8 + c0 * 2;
                float bx = sbias[coll], by = sbias[coll + 1];
                #pragma unroll
                for (int half_ = 0; half_ < 2; half_++) {
                    int row = row0 + half_ * 8;
                    if (row < M) {
                        float vx = fmaxf(acc[mf][nf][half_ * 2 + 0] + bx, 0.0f);
                        float vy = fmaxf(acc[mf][nf][half_ * 2 + 1] + by, 0.0f);
                        int cx = bn + coll;
                        int p = (cx & 31) >> 1;
                        int pp = ((p & 3) << 2) | (p >> 2);
                        __half2* dst = (__half2*)((__half*)Cout +
                                       (size_t)row * DIM_FC + (cx & ~31) + 2 * pp);
                        *dst = __floats2half2_rn(vx, vy);
                    }
                }
            }
        }
    } else {
        #pragma unroll
        for (int mf = 0; mf < 4; mf++) {
            #pragma unroll
            for (int half_ = 0; half_ < 2; half_++) {
                float p0 = 0.f, p1 = 0.f, p2 = 0.f;
                #pragma unroll
                for (int nf = 0; nf < 4; nf++) {
                    int coll = wn * 32 + nf * 8 + c0 * 2;
                    float vx = fmaxf(acc[mf][nf][half_ * 2 + 0] + sbias[coll], 0.0f);
                    float vy = fmaxf(acc[mf][nf][half_ * 2 + 1] + sbias[coll + 1], 0.0f);
                    p0 += vx * sW3[coll * 3 + 0] + vy * sW3[coll * 3 + 3];
                    p1 += vx * sW3[coll * 3 + 1] + vy * sW3[coll * 3 + 4];
                    p2 += vx * sW3[coll * 3 + 2] + vy * sW3[coll * 3 + 5];
                }
                p0 += __shfl_xor_sync(0xFFFFFFFFu, p0, 1);
                p1 += __shfl_xor_sync(0xFFFFFFFFu, p1, 1);
                p2 += __shfl_xor_sync(0xFFFFFFFFu, p2, 1);
                p0 += __shfl_xor_sync(0xFFFFFFFFu, p0, 2);
                p1 += __shfl_xor_sync(0xFFFFFFFFu, p1, 2);
                p2 += __shfl_xor_sync(0xFFFFFFFFu, p2, 2);
                if (c0 == 0) {
                    int lr = wm * 64 + mf * 16 + g + half_ * 8;
                    sP[wn][lr][0] = p0;
                    sP[wn][lr][1] = p1;
                    sP[wn][lr][2] = p2;
                }
            }
        }
        __syncthreads();
        float* part = (float*)Cout + (size_t)blockIdx.x * NLINES * NLAB;
        for (int i = tid; i < BM * NLAB; i += 256) {
            int lr = i / NLAB, lab = i % NLAB;
            int row = bm + lr;
            if (row < M)
                part[(size_t)row * NLAB + lab] =
                    sP[0][lr][lab] + sP[1][lr][lab] + sP[2][lr][lab] + sP[3][lr][lab];
        }
    }
}

// ---------------- kernel 5: reduce 8 partials + bias -> out ----------------
__global__ void reduce_out_kernel(const float* __restrict__ b3, float* __restrict__ out) {
    int i = blockIdx.x * 256 + threadIdx.x;
    if (i < NLINES * NLAB) {
        int lab = i % NLAB;
        float s = b3[lab];
        #pragma unroll
        for (int p = 0; p < 8; p++) s += g_part[p * NLINES * NLAB + i];
        out[i] = s;
    }
}

// ---------------- launch ---------------------------------------------------
extern "C" void kernel_launch(void* const* d_in, const int* in_sizes, int n_in,
                              void* d_out, int out_size) {
    const float* jloc = (const float*)d_in[0];
    const float* joff = (const float*)d_in[1];
    const float* loi  = (const float*)d_in[2];
    const int*   edge = (const int*)d_in[3];
    const float* W1   = (const float*)d_in[4];
    const float* b1   = (const float*)d_in[5];
    const float* W2   = (const float*)d_in[6];
    const float* b2   = (const float*)d_in[7];
    const float* W3   = (const float*)d_in[8];
    const float* b3   = (const float*)d_in[9];
    float* out = (float*)d_out;

    const int GEMM_SMEM = NSTG * STAGE * sizeof(__half);   // 65536 B
    cudaFuncSetAttribute(hgemm_kernel<0>,
                         cudaFuncAttributeMaxDynamicSharedMemorySize, GEMM_SMEM);
    cudaFuncSetAttribute(hgemm_kernel<1>,
                         cudaFuncAttributeMaxDynamicSharedMemorySize, GEMM_SMEM);

    __half *feats, *h1, *w1T, *w2T;
    float *part;
    cudaGetSymbolAddress((void**)&feats, g_feats);
    cudaGetSymbolAddress((void**)&h1, g_h1);
    cudaGetSymbolAddress((void**)&w1T, g_w1T);
    cudaGetSymbolAddress((void**)&w2T, g_w2T);
    cudaGetSymbolAddress((void**)&part, g_part);

    topk_juncs_kernel<<<1, 1024>>>(jloc, joff);
    transpose_loi_kernel<<<dim3(NPIX / 32, DIM_LOI / 32), dim3(32, 8)>>>(loi);
    transposeW_kernel<<<dim3(32, 32, 2), dim3(32, 8)>>>(W1, W2);
    sample_kernel<<<NLINES, 128>>>(edge);

    dim3 ggrid(DIM_FC / BN, (NLINES + BM - 1) / BM);
    hgemm_kernel<0><<<ggrid, 256, GEMM_SMEM>>>(feats, w1T, b1, nullptr, h1, NLINES);
    hgemm_kernel<1><<<ggrid, 256, GEMM_SMEM>>>(h1, w2T, b2, W3, part, NLINES);

    reduce_out_kernel<<<(NLINES * NLAB + 255) / 256, 256>>>(b3, out);
}

// round 12
// speedup vs baseline: 6.3920x; 1.0587x over previous
#include <cuda_runtime.h>
#include <cuda_fp16.h>
#include <math.h>
#include <cstdint>

#define HW 128
#define NPIX (HW*HW)          // 16384
#define TOPK 300
#define NLINES 20000
#define DIM_LOI 128
#define NPTS0 32
#define NPTS1 8
#define DIM_FC 1024
#define NLAB 3

// pair-permutation within a 32-k block (16 pairs): p' = (p&3)*4 + (p>>2)
__host__ __device__ __forceinline__ int khperm(int k) {
    int p = k >> 1;
    int pp = ((p & 3) << 2) | (p >> 2);
    return (pp << 1) | (k & 1);
}

// ---------------- scratch (device globals; no allocation allowed) ----------
__device__ __align__(16) __half g_loiTh[NPIX * DIM_LOI];   // [hw][c] fp16 4 MB
__device__ __align__(16) float  g_juncs[TOPK * 2];
__device__ __align__(16) __half g_feats[NLINES * DIM_FC];  // permuted fp16
__device__ __align__(16) __half g_h1[NLINES * DIM_FC];     // permuted fp16
__device__ __align__(16) __half g_w1T[DIM_FC * DIM_FC];    // W1^T [N][kperm]
__device__ __align__(16) __half g_w2T[DIM_FC * DIM_FC];    // W2^T [N][kperm]
__device__ __align__(16) float  g_part[8 * NLINES * NLAB]; // fused-out partials

// ======================= PTX helpers ========================================
__device__ __forceinline__ uint32_t smem_u32(const void* p) {
    uint32_t a;
    asm("{ .reg .u64 t; cvta.to.shared.u64 t, %1; cvt.u32.u64 %0, t; }" : "=r"(a) : "l"(p));
    return a;
}
#define CP_ASYNC16(sm, g) \
    asm volatile("cp.async.cg.shared.global [%0], [%1], 16;" :: "r"(sm), "l"(g) : "memory")
#define CP_COMMIT() asm volatile("cp.async.commit_group;" ::: "memory")
#define CP_WAIT(n)  asm volatile("cp.async.wait_group %0;" :: "n"(n) : "memory")

__device__ __forceinline__ void mma_f16(float* c,
                                        uint32_t a0, uint32_t a1, uint32_t a2, uint32_t a3,
                                        uint32_t b0, uint32_t b1) {
    asm volatile(
        "mma.sync.aligned.m16n8k16.row.col.f32.f16.f16.f32 "
        "{%0,%1,%2,%3}, {%4,%5,%6,%7}, {%8,%9}, {%0,%1,%2,%3};"
        : "+f"(c[0]), "+f"(c[1]), "+f"(c[2]), "+f"(c[3])
        : "r"(a0), "r"(a1), "r"(a2), "r"(a3), "r"(b0), "r"(b1));
}

// ---------------- kernel 1: NMS + compact + small bitonic top-k ------------
#define SORTN 4096
__global__ void topk_juncs_kernel(const float* __restrict__ jloc,
                                  const float* __restrict__ joff) {
    __shared__ unsigned long long keys[SORTN];
    __shared__ int cnt;
    int tid = threadIdx.x;
    if (tid == 0) cnt = 0;
    #pragma unroll
    for (int i = tid; i < SORTN; i += 1024) keys[i] = 0ull;
    __syncthreads();

    for (int i = tid; i < NPIX; i += 1024) {
        int y = i >> 7, x = i & 127;
        float v = jloc[i];
        float m = v;
        #pragma unroll
        for (int dy = -1; dy <= 1; dy++)
            #pragma unroll
            for (int dx = -1; dx <= 1; dx++) {
                int yy = y + dy, xx = x + dx;
                if (yy >= 0 && yy < HW && xx >= 0 && xx < HW)
                    m = fmaxf(m, jloc[yy * HW + xx]);
            }
        if (v == m && v > 0.0f) {
            int p = atomicAdd(&cnt, 1);
            if (p < SORTN)
                keys[p] = ((unsigned long long)__float_as_uint(v) << 32)
                        | (unsigned long long)(0xFFFFFFFFu - (unsigned)i);
        }
    }
    __syncthreads();

    for (int k = 2; k <= SORTN; k <<= 1) {
        for (int j = k >> 1; j > 0; j >>= 1) {
            #pragma unroll
            for (int i = tid; i < SORTN; i += 1024) {
                int ixj = i ^ j;
                if (ixj > i) {
                    unsigned long long a = keys[i], b = keys[ixj];
                    bool up = ((i & k) == 0);
                    if ((a < b) == up) { keys[i] = b; keys[ixj] = a; }
                }
            }
            __syncthreads();
        }
    }

    if (tid < TOPK) {
        unsigned long long key = keys[tid];
        unsigned idx = 0xFFFFFFFFu - (unsigned)(key & 0xFFFFFFFFull);
        float j0 = joff[idx];
        float j1 = joff[NPIX + idx];
        float sx = 1.0f / (1.0f + expf(-j0));
        float sy = 1.0f / (1.0f + expf(-j1));
        g_juncs[2 * tid + 0] = (float)(idx & 127) + sx;
        g_juncs[2 * tid + 1] = (float)(idx >> 7) + sy;
    }
}

// ---------------- kernel 2a: transpose loi [C][HW*HW] -> [HW*HW][C] fp16 ---
__global__ void transpose_loi_kernel(const float* __restrict__ in) {
    __shared__ float tile[32][33];
    int p0 = blockIdx.x * 32;
    int c0 = blockIdx.y * 32;
    int tx = threadIdx.x, ty = threadIdx.y;   // 32 x 8
    #pragma unroll
    for (int i = 0; i < 32; i += 8)
        tile[ty + i][tx] = in[(size_t)(c0 + ty + i) * NPIX + p0 + tx];
    __syncthreads();
    #pragma unroll
    for (int i = 0; i < 32; i += 8)
        g_loiTh[(size_t)(p0 + ty + i) * DIM_LOI + c0 + tx] =
            __float2half_rn(tile[tx][ty + i]);
}

// ---------------- kernel 2b: both W -> W^T with k-perm + fp16 (z = which) --
__global__ void transposeW_kernel(const float* __restrict__ W1,
                                  const float* __restrict__ W2) {
    __shared__ float tile[32][33];
    const float* in = blockIdx.z ? W2 : W1;
    __half* out = blockIdx.z ? g_w2T : g_w1T;
    int p0 = blockIdx.x * 32;   // n block
    int c0 = blockIdx.y * 32;   // k block
    int tx = threadIdx.x, ty = threadIdx.y;   // 32 x 8
    #pragma unroll
    for (int i = 0; i < 32; i += 8)
        tile[ty + i][tx] = in[(size_t)(c0 + ty + i) * DIM_FC + p0 + tx];
    __syncthreads();
    #pragma unroll
    for (int i = 0; i < 32; i += 8)
        out[(size_t)(p0 + ty + i) * DIM_FC + c0 + khperm(tx)] =
            __float2half_rn(tile[tx][ty + i]);
}

// ---------------- kernel 3: line sampling + bilinear + group max -----------
// 256 threads, 2 lines per block. Per line: pg = point group 0..7, cq = 8-ch
// chunk 0..15. Staging smem is [line][pg][ch(pad 136)] -> conflict-free STS.128.
__global__ void sample_kernel(const int* __restrict__ edge) {
    __shared__ int   s_off[2][NPTS0][4];
    __shared__ float s_w[2][NPTS0][4];
    __shared__ __align__(16) float s_out[2][8][136];

    int n0 = blockIdx.x * 2;
    int tid = threadIdx.x;
    int li  = tid >> 7;          // which line (0/1)
    int t128 = tid & 127;
    int pg = t128 >> 4;          // maxpool group 0..7
    int cq = t128 & 15;          // 8-channel chunk (16 B fp16)

    if (tid < 64) {
        int l = tid >> 5;        // line
        int pt = tid & 31;       // point
        int n = n0 + l;
        int e0 = edge[2 * n + 0];
        int e1 = edge[2 * n + 1];
        float Ux = g_juncs[2 * e0 + 0], Uy = g_juncs[2 * e0 + 1];
        float Vx = g_juncs[2 * e1 + 0], Vy = g_juncs[2 * e1 + 1];
        float t = (float)pt * (1.0f / 31.0f);
        float px = Ux * t + Vx * (1.0f - t) - 0.5f;
        float py = Uy * t + Vy * (1.0f - t) - 0.5f;
        float x0 = fminf(fmaxf(floorf(px), 0.0f), 127.0f);
        float y0 = fminf(fmaxf(floorf(py), 0.0f), 127.0f);
        float x1 = fminf(x0 + 1.0f, 127.0f);
        float y1 = fminf(y0 + 1.0f, 127.0f);
        int ix0 = (int)x0, iy0 = (int)y0, ix1 = (int)x1, iy1 = (int)y1;
        s_off[l][pt][0] = (iy0 * HW + ix0) * DIM_LOI;
        s_off[l][pt][1] = (iy1 * HW + ix0) * DIM_LOI;
        s_off[l][pt][2] = (iy0 * HW + ix1) * DIM_LOI;
        s_off[l][pt][3] = (iy1 * HW + ix1) * DIM_LOI;
        s_w[l][pt][0] = (y1 - py) * (x1 - px);
        s_w[l][pt][1] = (py - y0) * (x1 - px);
        s_w[l][pt][2] = (y1 - py) * (px - x0);
        s_w[l][pt][3] = (py - y0) * (px - x0);
    }
    __syncthreads();

    float m[8];
    #pragma unroll
    for (int i = 0; i < 8; i++) m[i] = -1e30f;

    #pragma unroll
    for (int k = 0; k < 4; k++) {
        int p = pg * 4 + k;
        float w0 = s_w[li][p][0], w1 = s_w[li][p][1];
        float w2 = s_w[li][p][2], w3 = s_w[li][p][3];
        uint4 u0 = *(const uint4*)(g_loiTh + s_off[li][p][0] + cq * 8);
        uint4 u1 = *(const uint4*)(g_loiTh + s_off[li][p][1] + cq * 8);
        uint4 u2 = *(const uint4*)(g_loiTh + s_off[li][p][2] + cq * 8);
        uint4 u3 = *(const uint4*)(g_loiTh + s_off[li][p][3] + cq * 8);
        const __half2* h0 = (const __half2*)&u0;
        const __half2* h1 = (const __half2*)&u1;
        const __half2* h2 = (const __half2*)&u2;
        const __half2* h3 = (const __half2*)&u3;
        #pragma unroll
        for (int j = 0; j < 4; j++) {
            float2 a = __half22float2(h0[j]);
            float2 b = __half22float2(h1[j]);
            float2 c = __half22float2(h2[j]);
            float2 d = __half22float2(h3[j]);
            float vx = w0 * a.x + w1 * b.x + w2 * c.x + w3 * d.x;
            float vy = w0 * a.y + w1 * b.y + w2 * c.y + w3 * d.y;
            m[2 * j + 0] = fmaxf(m[2 * j + 0], vx);
            m[2 * j + 1] = fmaxf(m[2 * j + 1], vy);
        }
    }

    // conflict-free staging: 16-lane group writes 256 contiguous bytes
    {
        float4* dst = (float4*)&s_out[li][pg][cq * 8];
        dst[0] = make_float4(m[0], m[1], m[2], m[3]);
        dst[1] = make_float4(m[4], m[5], m[6], m[7]);
    }
    __syncthreads();

    // emit permuted fp16 feats: feature f = ch*8 + pg  ->  s_out[li][f&7][f>>3]
    {
        size_t base = (size_t)(n0 + li) * DIM_FC;
        #pragma unroll
        for (int r = 0; r < 8; r++) {
            int f = t128 + 128 * r;
            float v = s_out[li][f & 7][f >> 3];
            int pos = (f & ~31) | khperm(f & 31);
            g_feats[base + pos] = __float2half_rn(v);
        }
    }
}

// ---------------- kernel 4: fp16 mma GEMM, 128x128 tile, 64x32 warp tile ---
// MODE 0: C = relu(A@BT^T + bias), fp16 k-permuted out
// MODE 1: fused final: partial[bx][row][lab] = sum_cols relu(acc+bias)*W3[col][lab]
#define BK 32                          // halves per k-tile (64 B per row)
#define NKT (DIM_FC / BK)              // 32
#define BM 128
#define BN 128
#define ATILE (BM * BK)                // 4096 halves
#define BTILE (BN * BK)
#define STAGE (ATILE + BTILE)          // 8192 halves = 16 KB
#define NSTG 4

template <int MODE>
__global__ __launch_bounds__(256, 2)
void hgemm_kernel(const __half* __restrict__ A, const __half* __restrict__ BT,
                  const float* __restrict__ bias, const float* __restrict__ W3,
                  void* __restrict__ Cout, int M)
{
    extern __shared__ __half smem[];   // [NSTG][A | B]
    __shared__ float sbias[BN];
    __shared__ float sW3[BN * NLAB];
    __shared__ float sP[4][BM][NLAB];
    const uint32_t sbase = smem_u32(smem);
    const int tid = threadIdx.x;
    const int lane = tid & 31;
    const int warp = tid >> 5;
    const int wm = warp & 1;           // 2 row slabs of 64
    const int wn = warp >> 1;          // 4 col slabs of 32
    const int bn = blockIdx.x * BN;
    const int bm = blockIdx.y * BM;

    if (tid < BN) sbias[tid] = bias[bn + tid];
    if (MODE == 1) {
        #pragma unroll
        for (int i = tid; i < BN * NLAB; i += 256) sW3[i] = W3[bn * NLAB + i];
    }

    const int lrow = tid >> 2;         // 0..63
    const int lchk = (tid & 3) * 8;    // halves (16 B chunk)

    const __half* gA[2];
    uint32_t sA[2];
    const __half* gB[2];
    uint32_t sB[2];
    #pragma unroll
    for (int i = 0; i < 2; i++) {
        int row = lrow + 64 * i;
        int ar = bm + row; if (ar >= M) ar = M - 1;
        gA[i] = A + (size_t)ar * DIM_FC + lchk;
        sA[i] = sbase + (row * BK + lchk) * 2;
        gB[i] = BT + (size_t)(bn + row) * DIM_FC + lchk;
        sB[i] = sbase + (ATILE + row * BK + lchk) * 2;
    }

    float acc[4][4][4];
    #pragma unroll
    for (int mf = 0; mf < 4; mf++)
        #pragma unroll
        for (int nf = 0; nf < 4; nf++)
            #pragma unroll
            for (int qq = 0; qq < 4; qq++) acc[mf][nf][qq] = 0.0f;

    #pragma unroll
    for (int j = 0; j < 2; j++) {
        uint32_t soff = j * STAGE * 2;
        int goff = j * BK;
        #pragma unroll
        for (int i = 0; i < 2; i++) {
            CP_ASYNC16(sA[i] + soff, gA[i] + goff);
            CP_ASYNC16(sB[i] + soff, gB[i] + goff);
        }
        CP_COMMIT();
    }

    const int g  = lane >> 2;
    const int c0 = lane & 3;

    for (int kt = 0; kt < NKT; kt++) {
        if (kt + 2 < NKT) {
            uint32_t soff = ((kt + 2) & (NSTG - 1)) * STAGE * 2;
            int goff = (kt + 2) * BK;
            #pragma unroll
            for (int i = 0; i < 2; i++) {
                CP_ASYNC16(sA[i] + soff, gA[i] + goff);
                CP_ASYNC16(sB[i] + soff, gB[i] + goff);
            }
        }
        CP_COMMIT();
        CP_WAIT(2);
        __syncthreads();

        const __half* As = smem + (kt & (NSTG - 1)) * STAGE;
        const __half* Bs = As + ATILE;

        uint4 av[4][2];
        #pragma unroll
        for (int mf = 0; mf < 4; mf++) {
            const __half* ap = As + (wm * 64 + mf * 16 + g) * BK + c0 * 8;
            av[mf][0] = *(const uint4*)ap;
            av[mf][1] = *(const uint4*)(ap + 8 * BK);
        }
        uint4 bv[4];
        #pragma unroll
        for (int nf = 0; nf < 4; nf++)
            bv[nf] = *(const uint4*)(Bs + (wn * 32 + nf * 8 + g) * BK + c0 * 8);

        #pragma unroll
        for (int mf = 0; mf < 4; mf++)
            #pragma unroll
            for (int nf = 0; nf < 4; nf++) {
                mma_f16(acc[mf][nf], av[mf][0].x, av[mf][1].x, av[mf][0].y, av[mf][1].y,
                        bv[nf].x, bv[nf].y);
                mma_f16(acc[mf][nf], av[mf][0].z, av[mf][1].z, av[mf][0].w, av[mf][1].w,
                        bv[nf].z, bv[nf].w);
            }
    }

    if (MODE == 0) {
        #pragma unroll
        for (int mf = 0; mf < 4; mf++) {
            int row0 = bm + wm * 64 + mf * 16 + g;
            #pragma unroll
            for (int nf = 0; nf < 4; nf++) {
                int coll = wn * 32 + nf * 8 + c0 * 2;
                float bx = sbias[coll], by = sbias[coll + 1];
                #pragma unroll
                for (int half_ = 0; half_ < 2; half_++) {
                    int row = row0 + half_ * 8;
                    if (row < M) {
                        float vx = fmaxf(acc[mf][nf][half_ * 2 + 0] + bx, 0.0f);
                        float vy = fmaxf(acc[mf][nf][half_ * 2 + 1] + by, 0.0f);
                        int cx = bn + coll;
                        int p = (cx & 31) >> 1;
                        int pp = ((p & 3) << 2) | (p >> 2);
                        __half2* dst = (__half2*)((__half*)Cout +
                                       (size_t)row * DIM_FC + (cx & ~31) + 2 * pp);
                        *dst = __floats2half2_rn(vx, vy);
                    }
                }
            }
        }
    } else {
        #pragma unroll
        for (int mf = 0; mf < 4; mf++) {
            #pragma unroll
            for (int half_ = 0; half_ < 2; half_++) {
                float p0 = 0.f, p1 = 0.f, p2 = 0.f;
                #pragma unroll
                for (int nf = 0; nf < 4; nf++) {
                    int coll = wn * 32 + nf * 8 + c0 * 2;
                    float vx = fmaxf(acc[mf][nf][half_ * 2 + 0] + sbias[coll], 0.0f);
                    float vy = fmaxf(acc[mf][nf][half_ * 2 + 1] + sbias[coll + 1], 0.0f);
                    p0 += vx * sW3[coll * 3 + 0] + vy * sW3[coll * 3 + 3];
                    p1 += vx * sW3[coll * 3 + 1] + vy * sW3[coll * 3 + 4];
                    p2 += vx * sW3[coll * 3 + 2] + vy * sW3[coll * 3 + 5];
                }
                p0 += __shfl_xor_sync(0xFFFFFFFFu, p0, 1);
                p1 += __shfl_xor_sync(0xFFFFFFFFu, p1, 1);
                p2 += __shfl_xor_sync(0xFFFFFFFFu, p2, 1);
                p0 += __shfl_xor_sync(0xFFFFFFFFu, p0, 2);
                p1 += __shfl_xor_sync(0xFFFFFFFFu, p1, 2);
                p2 += __shfl_xor_sync(0xFFFFFFFFu, p2, 2);
                if (c0 == 0) {
                    int lr = wm * 64 + mf * 16 + g + half_ * 8;
                    sP[wn][lr][0] = p0;
                    sP[wn][lr][1] = p1;
                    sP[wn][lr][2] = p2;
                }
            }
        }
        __syncthreads();
        float* part = (float*)Cout + (size_t)blockIdx.x * NLINES * NLAB;
        for (int i = tid; i < BM * NLAB; i += 256) {
            int lr = i / NLAB, lab = i % NLAB;
            int row = bm + lr;
            if (row < M)
                part[(size_t)row * NLAB + lab] =
                    sP[0][lr][lab] + sP[1][lr][lab] + sP[2][lr][lab] + sP[3][lr][lab];
        }
    }
}

// ---------------- kernel 5: reduce 8 partials + bias -> out ----------------
__global__ void reduce_out_kernel(const float* __restrict__ b3, float* __restrict__ out) {
    int i = blockIdx.x * 256 + threadIdx.x;
    if (i < NLINES * NLAB) {
        int lab = i % NLAB;
        float s = b3[lab];
        #pragma unroll
        for (int p = 0; p < 8; p++) s += g_part[p * NLINES * NLAB + i];
        out[i] = s;
    }
}

// ---------------- launch ---------------------------------------------------
extern "C" void kernel_launch(void* const* d_in, const int* in_sizes, int n_in,
                              void* d_out, int out_size) {
    const float* jloc = (const float*)d_in[0];
    const float* joff = (const float*)d_in[1];
    const float* loi  = (const float*)d_in[2];
    const int*   edge = (const int*)d_in[3];
    const float* W1   = (const float*)d_in[4];
    const float* b1   = (const float*)d_in[5];
    const float* W2   = (const float*)d_in[6];
    const float* b2   = (const float*)d_in[7];
    const float* W3   = (const float*)d_in[8];
    const float* b3   = (const float*)d_in[9];
    float* out = (float*)d_out;

    const int GEMM_SMEM = NSTG * STAGE * sizeof(__half);   // 65536 B
    cudaFuncSetAttribute(hgemm_kernel<0>,
                         cudaFuncAttributeMaxDynamicSharedMemorySize, GEMM_SMEM);
    cudaFuncSetAttribute(hgemm_kernel<1>,
                         cudaFuncAttributeMaxDynamicSharedMemorySize, GEMM_SMEM);

    __half *feats, *h1, *w1T, *w2T;
    float *part;
    cudaGetSymbolAddress((void**)&feats, g_feats);
    cudaGetSymbolAddress((void**)&h1, g_h1);
    cudaGetSymbolAddress((void**)&w1T, g_w1T);
    cudaGetSymbolAddress((void**)&w2T, g_w2T);
    cudaGetSymbolAddress((void**)&part, g_part);

    topk_juncs_kernel<<<1, 1024>>>(jloc, joff);
    transpose_loi_kernel<<<dim3(NPIX / 32, DIM_LOI / 32), dim3(32, 8)>>>(loi);
    transposeW_kernel<<<dim3(32, 32, 2), dim3(32, 8)>>>(W1, W2);
    sample_kernel<<<NLINES / 2, 256>>>(edge);

    dim3 ggrid(DIM_FC / BN, (NLINES + BM - 1) / BM);
    hgemm_kernel<0><<<ggrid, 256, GEMM_SMEM>>>(feats, w1T, b1, nullptr, h1, NLINES);
    hgemm_kernel<1><<<ggrid, 256, GEMM_SMEM>>>(h1, w2T, b2, W3, part, NLINES);

    reduce_out_kernel<<<(NLINES * NLAB + 255) / 256, 256>>>(b3, out);
}

// round 13
// speedup vs baseline: 6.6178x; 1.0353x over previous
#include <cuda_runtime.h>
#include <cuda_fp16.h>
#include <math.h>
#include <cstdint>

#define HW 128
#define NPIX (HW*HW)          // 16384
#define TOPK 300
#define NLINES 20000
#define DIM_LOI 128
#define NPTS0 32
#define NPTS1 8
#define DIM_FC 1024
#define NLAB 3

// pair-permutation within a 32-k block (16 pairs): p' = (p&3)*4 + (p>>2)
__host__ __device__ __forceinline__ int khperm(int k) {
    int p = k >> 1;
    int pp = ((p & 3) << 2) | (p >> 2);
    return (pp << 1) | (k & 1);
}

// ---------------- scratch (device globals; no allocation allowed) ----------
__device__ __align__(16) __half g_loiTh[NPIX * DIM_LOI];   // [hw][c] fp16 4 MB
__device__ __align__(16) float  g_juncs[TOPK * 2];
__device__ __align__(16) __half g_feats[NLINES * DIM_FC];  // permuted fp16
__device__ __align__(16) __half g_h1[NLINES * DIM_FC];     // permuted fp16
__device__ __align__(16) __half g_w1T[DIM_FC * DIM_FC];    // W1^T [N][kperm]
__device__ __align__(16) __half g_w2T[DIM_FC * DIM_FC];    // W2^T [N][kperm]
__device__ __align__(16) float  g_part[8 * NLINES * NLAB]; // fused-out partials

// ======================= PTX helpers ========================================
__device__ __forceinline__ uint32_t smem_u32(const void* p) {
    uint32_t a;
    asm("{ .reg .u64 t; cvta.to.shared.u64 t, %1; cvt.u32.u64 %0, t; }" : "=r"(a) : "l"(p));
    return a;
}
#define CP_ASYNC16(sm, g) \
    asm volatile("cp.async.cg.shared.global [%0], [%1], 16;" :: "r"(sm), "l"(g) : "memory")
#define CP_COMMIT() asm volatile("cp.async.commit_group;" ::: "memory")
#define CP_WAIT(n)  asm volatile("cp.async.wait_group %0;" :: "n"(n) : "memory")

__device__ __forceinline__ void mma_f16(float* c,
                                        uint32_t a0, uint32_t a1, uint32_t a2, uint32_t a3,
                                        uint32_t b0, uint32_t b1) {
    asm volatile(
        "mma.sync.aligned.m16n8k16.row.col.f32.f16.f16.f32 "
        "{%0,%1,%2,%3}, {%4,%5,%6,%7}, {%8,%9}, {%0,%1,%2,%3};"
        : "+f"(c[0]), "+f"(c[1]), "+f"(c[2]), "+f"(c[3])
        : "r"(a0), "r"(a1), "r"(a2), "r"(a3), "r"(b0), "r"(b1));
}

// ---------------- kernel 1: NMS + compact + small bitonic top-k ------------
#define SORTN 4096
__global__ void topk_juncs_kernel(const float* __restrict__ jloc,
                                  const float* __restrict__ joff) {
    __shared__ unsigned long long keys[SORTN];
    __shared__ int cnt;
    int tid = threadIdx.x;
    if (tid == 0) cnt = 0;
    #pragma unroll
    for (int i = tid; i < SORTN; i += 1024) keys[i] = 0ull;
    __syncthreads();

    for (int i = tid; i < NPIX; i += 1024) {
        int y = i >> 7, x = i & 127;
        float v = jloc[i];
        float m = v;
        #pragma unroll
        for (int dy = -1; dy <= 1; dy++)
            #pragma unroll
            for (int dx = -1; dx <= 1; dx++) {
                int yy = y + dy, xx = x + dx;
                if (yy >= 0 && yy < HW && xx >= 0 && xx < HW)
                    m = fmaxf(m, jloc[yy * HW + xx]);
            }
        if (v == m && v > 0.0f) {
            int p = atomicAdd(&cnt, 1);
            if (p < SORTN)
                keys[p] = ((unsigned long long)__float_as_uint(v) << 32)
                        | (unsigned long long)(0xFFFFFFFFu - (unsigned)i);
        }
    }
    __syncthreads();

    for (int k = 2; k <= SORTN; k <<= 1) {
        for (int j = k >> 1; j > 0; j >>= 1) {
            #pragma unroll
            for (int i = tid; i < SORTN; i += 1024) {
                int ixj = i ^ j;
                if (ixj > i) {
                    unsigned long long a = keys[i], b = keys[ixj];
                    bool up = ((i & k) == 0);
                    if ((a < b) == up) { keys[i] = b; keys[ixj] = a; }
                }
            }
            __syncthreads();
        }
    }

    if (tid < TOPK) {
        unsigned long long key = keys[tid];
        unsigned idx = 0xFFFFFFFFu - (unsigned)(key & 0xFFFFFFFFull);
        float j0 = joff[idx];
        float j1 = joff[NPIX + idx];
        float sx = 1.0f / (1.0f + expf(-j0));
        float sy = 1.0f / (1.0f + expf(-j1));
        g_juncs[2 * tid + 0] = (float)(idx & 127) + sx;
        g_juncs[2 * tid + 1] = (float)(idx >> 7) + sy;
    }
}

// ---------------- kernel 2a: transpose loi [C][HW*HW] -> [HW*HW][C] fp16 ---
__global__ void transpose_loi_kernel(const float* __restrict__ in) {
    __shared__ float tile[32][33];
    int p0 = blockIdx.x * 32;
    int c0 = blockIdx.y * 32;
    int tx = threadIdx.x, ty = threadIdx.y;   // 32 x 8
    #pragma unroll
    for (int i = 0; i < 32; i += 8)
        tile[ty + i][tx] = in[(size_t)(c0 + ty + i) * NPIX + p0 + tx];
    __syncthreads();
    #pragma unroll
    for (int i = 0; i < 32; i += 8)
        g_loiTh[(size_t)(p0 + ty + i) * DIM_LOI + c0 + tx] =
            __float2half_rn(tile[tx][ty + i]);
}

// ---------------- kernel 2b: both W -> W^T with k-perm + fp16 (z = which) --
__global__ void transposeW_kernel(const float* __restrict__ W1,
                                  const float* __restrict__ W2) {
    __shared__ float tile[32][33];
    const float* in = blockIdx.z ? W2 : W1;
    __half* out = blockIdx.z ? g_w2T : g_w1T;
    int p0 = blockIdx.x * 32;   // n block
    int c0 = blockIdx.y * 32;   // k block
    int tx = threadIdx.x, ty = threadIdx.y;   // 32 x 8
    #pragma unroll
    for (int i = 0; i < 32; i += 8)
        tile[ty + i][tx] = in[(size_t)(c0 + ty + i) * DIM_FC + p0 + tx];
    __syncthreads();
    #pragma unroll
    for (int i = 0; i < 32; i += 8)
        out[(size_t)(p0 + ty + i) * DIM_FC + c0 + khperm(tx)] =
            __float2half_rn(tile[tx][ty + i]);
}

// ---------------- kernel 3: line sampling + bilinear + group max -----------
// 256 threads, 2 lines per block. Per line: pg = point group 0..7, cq = 8-ch
// chunk 0..15. Staging smem is [line][pg][ch(pad 136)] -> conflict-free STS.128.
__global__ void sample_kernel(const int* __restrict__ edge) {
    __shared__ int   s_off[2][NPTS0][4];
    __shared__ float s_w[2][NPTS0][4];
    __shared__ __align__(16) float s_out[2][8][136];

    int n0 = blockIdx.x * 2;
    int tid = threadIdx.x;
    int li  = tid >> 7;          // which line (0/1)
    int t128 = tid & 127;
    int pg = t128 >> 4;          // maxpool group 0..7
    int cq = t128 & 15;          // 8-channel chunk (16 B fp16)

    if (tid < 64) {
        int l = tid >> 5;        // line
        int pt = tid & 31;       // point
        int n = n0 + l;
        int e0 = edge[2 * n + 0];
        int e1 = edge[2 * n + 1];
        float Ux = g_juncs[2 * e0 + 0], Uy = g_juncs[2 * e0 + 1];
        float Vx = g_juncs[2 * e1 + 0], Vy = g_juncs[2 * e1 + 1];
        float t = (float)pt * (1.0f / 31.0f);
        float px = Ux * t + Vx * (1.0f - t) - 0.5f;
        float py = Uy * t + Vy * (1.0f - t) - 0.5f;
        float x0 = fminf(fmaxf(floorf(px), 0.0f), 127.0f);
        float y0 = fminf(fmaxf(floorf(py), 0.0f), 127.0f);
        float x1 = fminf(x0 + 1.0f, 127.0f);
        float y1 = fminf(y0 + 1.0f, 127.0f);
        int ix0 = (int)x0, iy0 = (int)y0, ix1 = (int)x1, iy1 = (int)y1;
        s_off[l][pt][0] = (iy0 * HW + ix0) * DIM_LOI;
        s_off[l][pt][1] = (iy1 * HW + ix0) * DIM_LOI;
        s_off[l][pt][2] = (iy0 * HW + ix1) * DIM_LOI;
        s_off[l][pt][3] = (iy1 * HW + ix1) * DIM_LOI;
        s_w[l][pt][0] = (y1 - py) * (x1 - px);
        s_w[l][pt][1] = (py - y0) * (x1 - px);
        s_w[l][pt][2] = (y1 - py) * (px - x0);
        s_w[l][pt][3] = (py - y0) * (px - x0);
    }
    __syncthreads();

    float m[8];
    #pragma unroll
    for (int i = 0; i < 8; i++) m[i] = -1e30f;

    #pragma unroll
    for (int k = 0; k < 4; k++) {
        int p = pg * 4 + k;
        float w0 = s_w[li][p][0], w1 = s_w[li][p][1];
        float w2 = s_w[li][p][2], w3 = s_w[li][p][3];
        uint4 u0 = *(const uint4*)(g_loiTh + s_off[li][p][0] + cq * 8);
        uint4 u1 = *(const uint4*)(g_loiTh + s_off[li][p][1] + cq * 8);
        uint4 u2 = *(const uint4*)(g_loiTh + s_off[li][p][2] + cq * 8);
        uint4 u3 = *(const uint4*)(g_loiTh + s_off[li][p][3] + cq * 8);
        const __half2* h0 = (const __half2*)&u0;
        const __half2* h1 = (const __half2*)&u1;
        const __half2* h2 = (const __half2*)&u2;
        const __half2* h3 = (const __half2*)&u3;
        #pragma unroll
        for (int j = 0; j < 4; j++) {
            float2 a = __half22float2(h0[j]);
            float2 b = __half22float2(h1[j]);
            float2 c = __half22float2(h2[j]);
            float2 d = __half22float2(h3[j]);
            float vx = w0 * a.x + w1 * b.x + w2 * c.x + w3 * d.x;
            float vy = w0 * a.y + w1 * b.y + w2 * c.y + w3 * d.y;
            m[2 * j + 0] = fmaxf(m[2 * j + 0], vx);
            m[2 * j + 1] = fmaxf(m[2 * j + 1], vy);
        }
    }

    // conflict-free staging: 16-lane group writes 256 contiguous bytes
    {
        float4* dst = (float4*)&s_out[li][pg][cq * 8];
        dst[0] = make_float4(m[0], m[1], m[2], m[3]);
        dst[1] = make_float4(m[4], m[5], m[6], m[7]);
    }
    __syncthreads();

    // emit permuted fp16 feats: feature f = ch*8 + pg  ->  s_out[li][f&7][f>>3]
    {
        size_t base = (size_t)(n0 + li) * DIM_FC;
        #pragma unroll
        for (int r = 0; r < 8; r++) {
            int f = t128 + 128 * r;
            float v = s_out[li][f & 7][f >> 3];
            int pos = (f & ~31) | khperm(f & 31);
            g_feats[base + pos] = __float2half_rn(v);
        }
    }
}

// ---------------- kernel 4: fp16 mma GEMM, 128x128 tile, 64x32 warp tile ---
// BK=64 (128 B rows), 3-stage cp.async ring, distance-1 prefetch, ONE
// __syncthreads per k-tile (write stage (kt+1)%3 vs laggard stage (kt-1)%3).
// 16B-chunk XOR swizzle (chunk ^= (row&1)<<2) keeps LDS.128 frag loads
// conflict-free with unpadded 128 B rows.
// MODE 0: C = relu(A@BT^T + bias), fp16 k-permuted out
// MODE 1: fused final: partial[bx][row][lab] = sum_cols relu(acc+bias)*W3[col][lab]
#define BK 64                          // halves per k-tile (128 B per row)
#define NKT (DIM_FC / BK)              // 16
#define BM 128
#define BN 128
#define ATILE (BM * BK)                // 8192 halves
#define BTILE (BN * BK)
#define STAGE (ATILE + BTILE)          // 16384 halves = 32 KB
#define NSTG 3

template <int MODE>
__global__ __launch_bounds__(256, 2)
void hgemm_kernel(const __half* __restrict__ A, const __half* __restrict__ BT,
                  const float* __restrict__ bias, const float* __restrict__ W3,
                  void* __restrict__ Cout, int M)
{
    extern __shared__ __half smem[];   // [NSTG][A | B]
    __shared__ float sbias[BN];
    __shared__ float sW3[BN * NLAB];
    __shared__ float sP[4][BM][NLAB];
    const uint32_t sbase = smem_u32(smem);
    const int tid = threadIdx.x;
    const int lane = tid & 31;
    const int warp = tid >> 5;
    const int wm = warp & 1;           // 2 row slabs of 64
    const int wn = warp >> 1;          // 4 col slabs of 32
    const int bn = blockIdx.x * BN;
    const int bm = blockIdx.y * BM;

    if (tid < BN) sbias[tid] = bias[bn + tid];
    if (MODE == 1) {
        #pragma unroll
        for (int i = tid; i < BN * NLAB; i += 256) sW3[i] = W3[bn * NLAB + i];
    }

    // global->smem: 128 B per row -> 8 threads/row (16 B chunks, xor-swizzled)
    const int lrow = tid >> 3;         // 0..31
    const int lchk = tid & 7;          // 16B chunk index
    const int schk = lchk ^ ((lrow & 1) << 2);   // swizzled chunk

    const __half* gA[4];
    uint32_t sA[4];
    const __half* gB[4];
    uint32_t sB[4];
    #pragma unroll
    for (int i = 0; i < 4; i++) {
        int row = lrow + 32 * i;       // parity(row) == parity(lrow)
        int ar = bm + row; if (ar >= M) ar = M - 1;
        gA[i] = A + (size_t)ar * DIM_FC + lchk * 8;
        sA[i] = sbase + (row * BK + schk * 8) * 2;
        gB[i] = BT + (size_t)(bn + row) * DIM_FC + lchk * 8;
        sB[i] = sbase + (ATILE + row * BK + schk * 8) * 2;
    }

    float acc[4][4][4];
    #pragma unroll
    for (int mf = 0; mf < 4; mf++)
        #pragma unroll
        for (int nf = 0; nf < 4; nf++)
            #pragma unroll
            for (int qq = 0; qq < 4; qq++) acc[mf][nf][qq] = 0.0f;

    // prologue: ktile 0 -> stage 0
    #pragma unroll
    for (int i = 0; i < 4; i++) {
        CP_ASYNC16(sA[i], gA[i]);
        CP_ASYNC16(sB[i], gB[i]);
    }
    CP_COMMIT();

    const int g  = lane >> 2;
    const int c0 = lane & 3;
    const int gx = (g & 1) << 2;       // frag chunk xor (row parity = g&1)

    int cs = 0;                        // current stage
    int ns = 1;                        // next stage
    for (int kt = 0; kt < NKT; kt++) {
        if (kt + 1 < NKT) {
            uint32_t soff = (uint32_t)ns * (STAGE * 2);
            int goff = (kt + 1) * BK;
            #pragma unroll
            for (int i = 0; i < 4; i++) {
                CP_ASYNC16(sA[i] + soff, gA[i] + goff);
                CP_ASYNC16(sB[i] + soff, gB[i] + goff);
            }
            CP_COMMIT();
            CP_WAIT(1);
        } else {
            CP_WAIT(0);
        }
        __syncthreads();

        const __half* As = smem + cs * STAGE;
        const __half* Bs = As + ATILE;

        #pragma unroll
        for (int h = 0; h < 2; h++) {  // two 32-k half-blocks
            const int choff = (((h << 2) | c0) ^ gx) * 8;   // halves
            uint4 av[4][2];
            #pragma unroll
            for (int mf = 0; mf < 4; mf++) {
                const __half* ap = As + (wm * 64 + mf * 16 + g) * BK + choff;
                av[mf][0] = *(const uint4*)ap;
                av[mf][1] = *(const uint4*)(ap + 8 * BK);
            }
            uint4 bv[4];
            #pragma unroll
            for (int nf = 0; nf < 4; nf++)
                bv[nf] = *(const uint4*)(Bs + (wn * 32 + nf * 8 + g) * BK + choff);

            #pragma unroll
            for (int mf = 0; mf < 4; mf++)
                #pragma unroll
                for (int nf = 0; nf < 4; nf++) {
                    mma_f16(acc[mf][nf], av[mf][0].x, av[mf][1].x, av[mf][0].y, av[mf][1].y,
                            bv[nf].x, bv[nf].y);
                    mma_f16(acc[mf][nf], av[mf][0].z, av[mf][1].z, av[mf][0].w, av[mf][1].w,
                            bv[nf].z, bv[nf].w);
                }
        }

        cs = ns;
        ns = (ns == NSTG - 1) ? 0 : ns + 1;
    }

    if (MODE == 0) {
        #pragma unroll
        for (int mf = 0; mf < 4; mf++) {
            int row0 = bm + wm * 64 + mf * 16 + g;
            #pragma unroll
            for (int nf = 0; nf < 4; nf++) {
                int coll = wn * 32 + nf * 8 + c0 * 2;
                float bx = sbias[coll], by = sbias[coll + 1];
                #pragma unroll
                for (int half_ = 0; half_ < 2; half_++) {
                    int row = row0 + half_ * 8;
                    if (row < M) {
                        float vx = fmaxf(acc[mf][nf][half_ * 2 + 0] + bx, 0.0f);
                        float vy = fmaxf(acc[mf][nf][half_ * 2 + 1] + by, 0.0f);
                        int cx = bn + coll;
                        int p = (cx & 31) >> 1;
                        int pp = ((p & 3) << 2) | (p >> 2);
                        __half2* dst = (__half2*)((__half*)Cout +
                                       (size_t)row * DIM_FC + (cx & ~31) + 2 * pp);
                        *dst = __floats2half2_rn(vx, vy);
                    }
                }
            }
        }
    } else {
        #pragma unroll
        for (int mf = 0; mf < 4; mf++) {
            #pragma unroll
            for (int half_ = 0; half_ < 2; half_++) {
                float p0 = 0.f, p1 = 0.f, p2 = 0.f;
                #pragma unroll
                for (int nf = 0; nf < 4; nf++) {
                    int coll = wn * 32 + nf * 8 + c0 * 2;
                    float vx = fmaxf(acc[mf][nf][half_ * 2 + 0] + sbias[coll], 0.0f);
                    float vy = fmaxf(acc[mf][nf][half_ * 2 + 1] + sbias[coll + 1], 0.0f);
                    p0 += vx * sW3[coll * 3 + 0] + vy * sW3[coll * 3 + 3];
                    p1 += vx * sW3[coll * 3 + 1] + vy * sW3[coll * 3 + 4];
                    p2 += vx * sW3[coll * 3 + 2] + vy * sW3[coll * 3 + 5];
                }
                p0 += __shfl_xor_sync(0xFFFFFFFFu, p0, 1);
                p1 += __shfl_xor_sync(0xFFFFFFFFu, p1, 1);
                p2 += __shfl_xor_sync(0xFFFFFFFFu, p2, 1);
                p0 += __shfl_xor_sync(0xFFFFFFFFu, p0, 2);
                p1 += __shfl_xor_sync(0xFFFFFFFFu, p1, 2);
                p2 += __shfl_xor_sync(0xFFFFFFFFu, p2, 2);
                if (c0 == 0) {
                    int lr = wm * 64 + mf * 16 + g + half_ * 8;
                    sP[wn][lr][0] = p0;
                    sP[wn][lr][1] = p1;
                    sP[wn][lr][2] = p2;
                }
            }
        }
        __syncthreads();
        float* part = (float*)Cout + (size_t)blockIdx.x * NLINES * NLAB;
        for (int i = tid; i < BM * NLAB; i += 256) {
            int lr = i / NLAB, lab = i % NLAB;
            int row = bm + lr;
            if (row < M)
                part[(size_t)row * NLAB + lab] =
                    sP[0][lr][lab] + sP[1][lr][lab] + sP[2][lr][lab] + sP[3][lr][lab];
        }
    }
}

// ---------------- kernel 5: reduce 8 partials + bias -> out ----------------
__global__ void reduce_out_kernel(const float* __restrict__ b3, float* __restrict__ out) {
    int i = blockIdx.x * 256 + threadIdx.x;
    if (i < NLINES * NLAB) {
        int lab = i % NLAB;
        float s = b3[lab];
        #pragma unroll
        for (int p = 0; p < 8; p++) s += g_part[p * NLINES * NLAB + i];
        out[i] = s;
    }
}

// ---------------- launch ---------------------------------------------------
extern "C" void kernel_launch(void* const* d_in, const int* in_sizes, int n_in,
                              void* d_out, int out_size) {
    const float* jloc = (const float*)d_in[0];
    const float* joff = (const float*)d_in[1];
    const float* loi  = (const float*)d_in[2];
    const int*   edge = (const int*)d_in[3];
    const float* W1   = (const float*)d_in[4];
    const float* b1   = (const float*)d_in[5];
    const float* W2   = (const float*)d_in[6];
    const float* b2   = (const float*)d_in[7];
    const float* W3   = (const float*)d_in[8];
    const float* b3   = (const float*)d_in[9];
    float* out = (float*)d_out;

    const int GEMM_SMEM = NSTG * STAGE * sizeof(__half);   // 98304 B
    cudaFuncSetAttribute(hgemm_kernel<0>,
                         cudaFuncAttributeMaxDynamicSharedMemorySize, GEMM_SMEM);
    cudaFuncSetAttribute(hgemm_kernel<1>,
                         cudaFuncAttributeMaxDynamicSharedMemorySize, GEMM_SMEM);

    __half *feats, *h1, *w1T, *w2T;
    float *part;
    cudaGetSymbolAddress((void**)&feats, g_feats);
    cudaGetSymbolAddress((void**)&h1, g_h1);
    cudaGetSymbolAddress((void**)&w1T, g_w1T);
    cudaGetSymbolAddress((void**)&w2T, g_w2T);
    cudaGetSymbolAddress((void**)&part, g_part);

    topk_juncs_kernel<<<1, 1024>>>(jloc, joff);
    transpose_loi_kernel<<<dim3(NPIX / 32, DIM_LOI / 32), dim3(32, 8)>>>(loi);
    transposeW_kernel<<<dim3(32, 32, 2), dim3(32, 8)>>>(W1, W2);
    sample_kernel<<<NLINES / 2, 256>>>(edge);

    dim3 ggrid(DIM_FC / BN, (NLINES + BM - 1) / BM);
    hgemm_kernel<0><<<ggrid, 256, GEMM_SMEM>>>(feats, w1T, b1, nullptr, h1, NLINES);
    hgemm_kernel<1><<<ggrid, 256, GEMM_SMEM>>>(h1, w2T, b2, W3, part, NLINES);

    reduce_out_kernel<<<(NLINES * NLAB + 255) / 256, 256>>>(b3, out);
}